// round 1
// baseline (speedup 1.0000x reference)
#include <cuda_runtime.h>

// Swin windowed attention, fp32 baseline (flash-style online softmax).
// Shapes: q,k,v [512,8,256,16]; table [961,8]; index [65536] int32; mask [64,256,256].
// out [512,256,128] fp32.

#define B_TOT 512
#define HEADS 8
#define NTOK  256
#define HD    16
#define NWIN  64
#define TAB   961
#define KB    32   // key block for online softmax

__global__ __launch_bounds__(256, 2)
void swin_attn_kernel(const float* __restrict__ q,
                      const float* __restrict__ k,
                      const float* __restrict__ v,
                      const float* __restrict__ table,
                      const int*   __restrict__ index,
                      const float* __restrict__ mask,
                      float* __restrict__ out)
{
    const int bh  = blockIdx.x;        // bh = b*8 + h
    const int b   = bh >> 3;
    const int h   = bh & 7;
    const int w   = b & (NWIN - 1);    // window id = b % 64
    const int tid = threadIdx.x;       // query row

    __shared__ float ksm[NTOK][HD];    // L2-normalized K rows
    __shared__ float vsm[NTOK][HD];    // raw V rows
    __shared__ float tcol[TAB];        // table column for this head

    // Stage table column h (bias gather becomes an LDS).
    for (int t = tid; t < TAB; t += 256) tcol[t] = table[t * HEADS + h];

    const size_t base = (size_t)bh * NTOK * HD;
    const float4* k4 = (const float4*)(k + base);
    const float4* v4 = (const float4*)(v + base);
    const float4* q4 = (const float4*)(q + base);

    // Normalize K row tid into smem; copy V row tid.
    {
        float4 a = k4[tid * 4 + 0];
        float4 c = k4[tid * 4 + 1];
        float4 e = k4[tid * 4 + 2];
        float4 g = k4[tid * 4 + 3];
        float ss = a.x*a.x + a.y*a.y + a.z*a.z + a.w*a.w
                 + c.x*c.x + c.y*c.y + c.z*c.z + c.w*c.w
                 + e.x*e.x + e.y*e.y + e.z*e.z + e.w*e.w
                 + g.x*g.x + g.y*g.y + g.z*g.z + g.w*g.w;
        float inv = rsqrtf(fmaxf(ss, 1e-24f));   // matches x / max(||x||, 1e-12)
        float4* kr = (float4*)ksm[tid];
        kr[0] = make_float4(a.x*inv, a.y*inv, a.z*inv, a.w*inv);
        kr[1] = make_float4(c.x*inv, c.y*inv, c.z*inv, c.w*inv);
        kr[2] = make_float4(e.x*inv, e.y*inv, e.z*inv, e.w*inv);
        kr[3] = make_float4(g.x*inv, g.y*inv, g.z*inv, g.w*inv);
        float4* vr = (float4*)vsm[tid];
        vr[0] = v4[tid * 4 + 0];
        vr[1] = v4[tid * 4 + 1];
        vr[2] = v4[tid * 4 + 2];
        vr[3] = v4[tid * 4 + 3];
    }

    // Normalize Q row tid into registers.
    float qr[HD];
    {
        float4 a = q4[tid * 4 + 0];
        float4 c = q4[tid * 4 + 1];
        float4 e = q4[tid * 4 + 2];
        float4 g = q4[tid * 4 + 3];
        float ss = a.x*a.x + a.y*a.y + a.z*a.z + a.w*a.w
                 + c.x*c.x + c.y*c.y + c.z*c.z + c.w*c.w
                 + e.x*e.x + e.y*e.y + e.z*e.z + e.w*e.w
                 + g.x*g.x + g.y*g.y + g.z*g.z + g.w*g.w;
        float inv = rsqrtf(fmaxf(ss, 1e-24f));
        qr[0]=a.x*inv;  qr[1]=a.y*inv;  qr[2]=a.z*inv;  qr[3]=a.w*inv;
        qr[4]=c.x*inv;  qr[5]=c.y*inv;  qr[6]=c.z*inv;  qr[7]=c.w*inv;
        qr[8]=e.x*inv;  qr[9]=e.y*inv;  qr[10]=e.z*inv; qr[11]=e.w*inv;
        qr[12]=g.x*inv; qr[13]=g.y*inv; qr[14]=g.z*inv; qr[15]=g.w*inv;
    }
    __syncthreads();

    float acc[HD];
    #pragma unroll
    for (int d = 0; d < HD; d++) acc[d] = 0.f;
    float mrun = -1e30f;
    float lrun = 0.f;

    const int4*   idxp = (const int4*)  (index + (size_t)tid * NTOK);
    const float4* mkp  = (const float4*)(mask + ((size_t)w * NTOK + tid) * NTOK);

    #pragma unroll 1
    for (int jb = 0; jb < NTOK / KB; jb++) {
        float s[KB];
        float bm = -1e30f;

        #pragma unroll
        for (int j4 = 0; j4 < KB / 4; j4++) {
            int4   iv = idxp[jb * (KB/4) + j4];
            float4 mv = mkp [jb * (KB/4) + j4];
            int idxs[4] = {iv.x, iv.y, iv.z, iv.w};
            float mvs[4] = {mv.x, mv.y, mv.z, mv.w};
            const int m0 = jb * KB + j4 * 4;
            #pragma unroll
            for (int jj = 0; jj < 4; jj++) {
                const int m = m0 + jj;
                float dot = tcol[idxs[jj]] + mvs[jj];  // bias + window mask
                const float4* kr = (const float4*)ksm[m];  // broadcast LDS
                float4 k0 = kr[0], k1 = kr[1], k2 = kr[2], k3 = kr[3];
                dot += qr[0]*k0.x  + qr[1]*k0.y  + qr[2]*k0.z  + qr[3]*k0.w;
                dot += qr[4]*k1.x  + qr[5]*k1.y  + qr[6]*k1.z  + qr[7]*k1.w;
                dot += qr[8]*k2.x  + qr[9]*k2.y  + qr[10]*k2.z + qr[11]*k2.w;
                dot += qr[12]*k3.x + qr[13]*k3.y + qr[14]*k3.z + qr[15]*k3.w;
                s[j4 * 4 + jj] = dot;
                bm = fmaxf(bm, dot);
            }
        }

        const float mnew = fmaxf(mrun, bm);
        const float cor  = __expf(mrun - mnew);   // exp(-inf)=0 on first block
        lrun *= cor;
        #pragma unroll
        for (int d = 0; d < HD; d++) acc[d] *= cor;

        #pragma unroll
        for (int jj = 0; jj < KB; jj++) {
            const float p = __expf(s[jj] - mnew);
            lrun += p;
            const float4* vr = (const float4*)vsm[jb * KB + jj];  // broadcast LDS
            float4 v0 = vr[0], v1 = vr[1], v2 = vr[2], v3 = vr[3];
            acc[0]  += p * v0.x;  acc[1]  += p * v0.y;  acc[2]  += p * v0.z;  acc[3]  += p * v0.w;
            acc[4]  += p * v1.x;  acc[5]  += p * v1.y;  acc[6]  += p * v1.z;  acc[7]  += p * v1.w;
            acc[8]  += p * v2.x;  acc[9]  += p * v2.y;  acc[10] += p * v2.z;  acc[11] += p * v2.w;
            acc[12] += p * v3.x;  acc[13] += p * v3.y;  acc[14] += p * v3.z;  acc[15] += p * v3.w;
        }
        mrun = mnew;
    }

    const float inv = 1.0f / lrun;
    // out[b][n=tid][h*16 + d]
    float4* o4 = (float4*)(out + ((size_t)(b * NTOK + tid)) * (HEADS * HD) + h * HD);
    o4[0] = make_float4(acc[0]*inv,  acc[1]*inv,  acc[2]*inv,  acc[3]*inv);
    o4[1] = make_float4(acc[4]*inv,  acc[5]*inv,  acc[6]*inv,  acc[7]*inv);
    o4[2] = make_float4(acc[8]*inv,  acc[9]*inv,  acc[10]*inv, acc[11]*inv);
    o4[3] = make_float4(acc[12]*inv, acc[13]*inv, acc[14]*inv, acc[15]*inv);
}

extern "C" void kernel_launch(void* const* d_in, const int* in_sizes, int n_in,
                              void* d_out, int out_size)
{
    const float* q     = (const float*)d_in[0];
    const float* k     = (const float*)d_in[1];
    const float* v     = (const float*)d_in[2];
    const float* table = (const float*)d_in[3];
    const int*   index = (const int*)  d_in[4];
    const float* mask  = (const float*)d_in[5];
    float* out = (float*)d_out;

    swin_attn_kernel<<<B_TOT * HEADS, 256>>>(q, k, v, table, index, mask, out);
}

// round 2
// speedup vs baseline: 1.8681x; 1.8681x over previous
#include <cuda_runtime.h>

// Swin windowed attention, fp32 with packed f32x2 FMA, fixed-max softmax,
// smem-staged (bias+mask) additive matrix.
// q,k,v [512,8,256,16] fp32; table [961,8]; index [65536] int32; mask [64,256,256].
// out [512,256,128] fp32.

#define B_TOT 512
#define HEADS 8
#define NTOK  256
#define HD    16
#define NWIN  64
#define TAB   961
#define KB    32          // keys per staged block
#define TPB   128         // 2 queries per thread

typedef unsigned long long u64;

__device__ __forceinline__ u64 ffma2(u64 a, u64 b, u64 c) {
    u64 d; asm("fma.rn.f32x2 %0, %1, %2, %3;" : "=l"(d) : "l"(a), "l"(b), "l"(c)); return d;
}
__device__ __forceinline__ u64 fmul2(u64 a, u64 b) {
    u64 d; asm("mul.rn.f32x2 %0, %1, %2;" : "=l"(d) : "l"(a), "l"(b)); return d;
}
__device__ __forceinline__ u64 fadd2(u64 a, u64 b) {
    u64 d; asm("add.rn.f32x2 %0, %1, %2;" : "=l"(d) : "l"(a), "l"(b)); return d;
}
__device__ __forceinline__ u64 pack2(float x, float y) {
    u64 d; asm("mov.b64 %0, {%1, %2};" : "=l"(d) : "f"(x), "f"(y)); return d;
}
__device__ __forceinline__ float2 unpack2(u64 a) {
    float2 r; asm("mov.b64 {%0, %1}, %2;" : "=f"(r.x), "=f"(r.y) : "l"(a)); return r;
}
__device__ __forceinline__ float hsum2(u64 a) { float2 r = unpack2(a); return r.x + r.y; }

// dynamic smem layout (bytes)
#define OFF_K   0
#define OFF_V   16384
#define OFF_A   32768                 // A[32][257] floats = 32896 B
#define OFF_T   (32768 + 32896)      // tcol, 961 floats
#define SMEM_BYTES (OFF_T + 3856)

__global__ __launch_bounds__(TPB, 3)
void swin_attn_kernel(const float* __restrict__ q,
                      const float* __restrict__ k,
                      const float* __restrict__ v,
                      const float* __restrict__ table,
                      const int*   __restrict__ index,
                      const float* __restrict__ mask,
                      float* __restrict__ out)
{
    extern __shared__ __align__(16) char smem[];
    float (*ksm)[HD]      = (float(*)[HD])(smem + OFF_K);
    float (*vsm)[HD]      = (float(*)[HD])(smem + OFF_V);
    float (*Asm)[NTOK+1]  = (float(*)[NTOK+1])(smem + OFF_A);  // A[j][i], stride 257
    float *tcol           = (float*)(smem + OFF_T);

    const int bh  = blockIdx.x;       // b*8 + h
    const int b   = bh >> 3;
    const int h   = bh & 7;
    const int w   = b & (NWIN - 1);
    const int tid = threadIdx.x;

    // table column for this head
    for (int t = tid; t < TAB; t += TPB) tcol[t] = table[t * HEADS + h];

    const size_t base = (size_t)bh * NTOK * HD;

    // normalize K rows into smem, copy V rows (each thread does 2 rows)
    for (int r = tid; r < NTOK; r += TPB) {
        const float4* kg = (const float4*)(k + base + (size_t)r * HD);
        float4 a = kg[0], c = kg[1], e = kg[2], g = kg[3];
        float ss = a.x*a.x + a.y*a.y + a.z*a.z + a.w*a.w
                 + c.x*c.x + c.y*c.y + c.z*c.z + c.w*c.w
                 + e.x*e.x + e.y*e.y + e.z*e.z + e.w*e.w
                 + g.x*g.x + g.y*g.y + g.z*g.z + g.w*g.w;
        float inv = rsqrtf(fmaxf(ss, 1e-24f));
        float4* kd = (float4*)&ksm[r][0];
        kd[0] = make_float4(a.x*inv, a.y*inv, a.z*inv, a.w*inv);
        kd[1] = make_float4(c.x*inv, c.y*inv, c.z*inv, c.w*inv);
        kd[2] = make_float4(e.x*inv, e.y*inv, e.z*inv, e.w*inv);
        kd[3] = make_float4(g.x*inv, g.y*inv, g.z*inv, g.w*inv);
        const float4* vg = (const float4*)(v + base + (size_t)r * HD);
        float4* vd = (float4*)&vsm[r][0];
        vd[0] = vg[0]; vd[1] = vg[1]; vd[2] = vg[2]; vd[3] = vg[3];
    }

    // normalize this thread's 2 query rows into packed f32x2 registers
    u64 qa[8], qb[8];
    {
        #pragma unroll
        for (int s = 0; s < 2; s++) {
            const int r = tid + s * TPB;
            const float4* qg = (const float4*)(q + base + (size_t)r * HD);
            float4 a = qg[0], c = qg[1], e = qg[2], g = qg[3];
            float ss = a.x*a.x + a.y*a.y + a.z*a.z + a.w*a.w
                     + c.x*c.x + c.y*c.y + c.z*c.z + c.w*c.w
                     + e.x*e.x + e.y*e.y + e.z*e.z + e.w*e.w
                     + g.x*g.x + g.y*g.y + g.z*g.z + g.w*g.w;
            float inv = rsqrtf(fmaxf(ss, 1e-24f));
            u64* qp = s ? qb : qa;
            qp[0] = pack2(a.x*inv, a.y*inv); qp[1] = pack2(a.z*inv, a.w*inv);
            qp[2] = pack2(c.x*inv, c.y*inv); qp[3] = pack2(c.z*inv, c.w*inv);
            qp[4] = pack2(e.x*inv, e.y*inv); qp[5] = pack2(e.z*inv, e.w*inv);
            qp[6] = pack2(g.x*inv, g.y*inv); qp[7] = pack2(g.z*inv, g.w*inv);
        }
    }

    u64 za[8], zb[8];
    #pragma unroll
    for (int i = 0; i < 8; i++) { za[i] = 0ULL; zb[i] = 0ULL; }
    float lra = 0.f, lrb = 0.f;

    const int*   idxg = index;
    const float* mg   = mask + (size_t)w * NTOK * NTOK;

    __syncthreads();   // tcol / K / V staged

    const int quad = tid & 7;        // 0..7  -> key cols quad*4 .. quad*4+3
    const int i0   = tid >> 3;       // 0..15 -> query rows i0 + 16*r

    #pragma unroll 1
    for (int jb = 0; jb < NTOK / KB; jb++) {
        // ---- stage A[j][i] = tcol[index[i,j]] + mask[w,i,j] (coalesced LDG) ----
        {
            const int j0 = jb * KB + (quad << 2);
            #pragma unroll
            for (int r2 = 0; r2 < 16; r2++) {
                const int i = i0 + (r2 << 4);
                int4   iv = *(const int4*)  (idxg + i * NTOK + j0);
                float4 mv = *(const float4*)(mg   + (size_t)i * NTOK + j0);
                Asm[(quad << 2) + 0][i] = tcol[iv.x] + mv.x;
                Asm[(quad << 2) + 1][i] = tcol[iv.y] + mv.y;
                Asm[(quad << 2) + 2][i] = tcol[iv.z] + mv.z;
                Asm[(quad << 2) + 3][i] = tcol[iv.w] + mv.w;
            }
        }
        __syncthreads();

        // ---- 32 keys: dot, exp(s-12), accumulate PV ----
        #pragma unroll 4
        for (int jj = 0; jj < KB; jj++) {
            const int m = jb * KB + jj;
            const ulonglong2* kr = (const ulonglong2*)&ksm[m][0];
            ulonglong2 x0 = kr[0], x1 = kr[1], x2 = kr[2], x3 = kr[3];

            u64 c0 = fmul2(qa[0], x0.x);
            u64 c1 = fmul2(qa[1], x0.y);
            c0 = ffma2(qa[2], x1.x, c0);
            c1 = ffma2(qa[3], x1.y, c1);
            c0 = ffma2(qa[4], x2.x, c0);
            c1 = ffma2(qa[5], x2.y, c1);
            c0 = ffma2(qa[6], x3.x, c0);
            c1 = ffma2(qa[7], x3.y, c1);

            u64 d0 = fmul2(qb[0], x0.x);
            u64 d1 = fmul2(qb[1], x0.y);
            d0 = ffma2(qb[2], x1.x, d0);
            d1 = ffma2(qb[3], x1.y, d1);
            d0 = ffma2(qb[4], x2.x, d0);
            d1 = ffma2(qb[5], x2.y, d1);
            d0 = ffma2(qb[6], x3.x, d0);
            d1 = ffma2(qb[7], x3.y, d1);

            float sa = hsum2(fadd2(c0, c1)) + Asm[jj][tid];
            float sb = hsum2(fadd2(d0, d1)) + Asm[jj][tid + TPB];

            // fixed shift: scores bounded well below 12, softmax is shift-invariant
            float pa = __expf(sa - 12.0f);
            float pb = __expf(sb - 12.0f);
            lra += pa; lrb += pb;
            u64 pa2 = pack2(pa, pa);
            u64 pb2 = pack2(pb, pb);

            const ulonglong2* vr = (const ulonglong2*)&vsm[m][0];
            ulonglong2 y0 = vr[0], y1 = vr[1], y2 = vr[2], y3 = vr[3];
            za[0] = ffma2(pa2, y0.x, za[0]); za[1] = ffma2(pa2, y0.y, za[1]);
            za[2] = ffma2(pa2, y1.x, za[2]); za[3] = ffma2(pa2, y1.y, za[3]);
            za[4] = ffma2(pa2, y2.x, za[4]); za[5] = ffma2(pa2, y2.y, za[5]);
            za[6] = ffma2(pa2, y3.x, za[6]); za[7] = ffma2(pa2, y3.y, za[7]);
            zb[0] = ffma2(pb2, y0.x, zb[0]); zb[1] = ffma2(pb2, y0.y, zb[1]);
            zb[2] = ffma2(pb2, y1.x, zb[2]); zb[3] = ffma2(pb2, y1.y, zb[3]);
            zb[4] = ffma2(pb2, y2.x, zb[4]); zb[5] = ffma2(pb2, y2.y, zb[5]);
            zb[6] = ffma2(pb2, y3.x, zb[6]); zb[7] = ffma2(pb2, y3.y, zb[7]);
        }
        __syncthreads();   // A consumed before next stage overwrites
    }

    // ---- epilogue: normalize and store both query rows ----
    {
        const float inva = 1.0f / lra;
        const u64 inva2 = pack2(inva, inva);
        float* op = out + ((size_t)(b * NTOK + tid)) * (HEADS * HD) + h * HD;
        ulonglong2* o2 = (ulonglong2*)op;
        ulonglong2 s0, s1, s2, s3;
        s0.x = fmul2(za[0], inva2); s0.y = fmul2(za[1], inva2);
        s1.x = fmul2(za[2], inva2); s1.y = fmul2(za[3], inva2);
        s2.x = fmul2(za[4], inva2); s2.y = fmul2(za[5], inva2);
        s3.x = fmul2(za[6], inva2); s3.y = fmul2(za[7], inva2);
        o2[0] = s0; o2[1] = s1; o2[2] = s2; o2[3] = s3;

        const float invb = 1.0f / lrb;
        const u64 invb2 = pack2(invb, invb);
        float* opb = out + ((size_t)(b * NTOK + tid + TPB)) * (HEADS * HD) + h * HD;
        ulonglong2* o2b = (ulonglong2*)opb;
        s0.x = fmul2(zb[0], invb2); s0.y = fmul2(zb[1], invb2);
        s1.x = fmul2(zb[2], invb2); s1.y = fmul2(zb[3], invb2);
        s2.x = fmul2(zb[4], invb2); s2.y = fmul2(zb[5], invb2);
        s3.x = fmul2(zb[6], invb2); s3.y = fmul2(zb[7], invb2);
        o2b[0] = s0; o2b[1] = s1; o2b[2] = s2; o2b[3] = s3;
    }
}

extern "C" void kernel_launch(void* const* d_in, const int* in_sizes, int n_in,
                              void* d_out, int out_size)
{
    const float* q     = (const float*)d_in[0];
    const float* k     = (const float*)d_in[1];
    const float* v     = (const float*)d_in[2];
    const float* table = (const float*)d_in[3];
    const int*   index = (const int*)  d_in[4];
    const float* mask  = (const float*)d_in[5];
    float* out = (float*)d_out;

    cudaFuncSetAttribute(swin_attn_kernel,
                         cudaFuncAttributeMaxDynamicSharedMemorySize, SMEM_BYTES);
    swin_attn_kernel<<<B_TOT * HEADS, TPB, SMEM_BYTES>>>(q, k, v, table, index, mask, out);
}

// round 6
// speedup vs baseline: 3.1628x; 1.6931x over previous
#include <cuda_runtime.h>
#include <cuda_fp16.h>
#include <cstdint>

// Swin windowed attention via mma.sync.m16n8k16 (HMMA, fp16 in / fp32 accum).
// q,k,v [512,8,256,16] f32; table [961,8]; index [65536] i32; mask [64,256,256]; out [512,256,128].

#define HEADS 8
#define NTOK  256
#define HD    16
#define TAB   961
#define TPB   256
#define SHIFT 4.0f

// dynamic smem layout (bytes)
#define OFF_Q   0                    // Qh [256][16] half  (8192)
#define OFF_K   8192                 // Kh [256][16] half  (8192)
#define OFF_V   16384                // Vt [16][264] half  (8448)
#define OFF_T   24832                // tcol 961 f32       (3844 -> 3872)
#define OFF_AB  28704                // ABw 8 warps x [32][36] f32
#define ABSTR   36                   // 144 B row stride: 16B-aligned float4 rows
#define SMEM_BYTES (OFF_AB + 8*32*ABSTR*4)

static __device__ __forceinline__ void mma16816(float c[4], const uint32_t a[4], const uint32_t b[2]) {
    asm volatile("mma.sync.aligned.m16n8k16.row.col.f32.f16.f16.f32 "
                 "{%0,%1,%2,%3}, {%4,%5,%6,%7}, {%8,%9}, {%0,%1,%2,%3};"
                 : "+f"(c[0]), "+f"(c[1]), "+f"(c[2]), "+f"(c[3])
                 : "r"(a[0]), "r"(a[1]), "r"(a[2]), "r"(a[3]), "r"(b[0]), "r"(b[1]));
}
static __device__ __forceinline__ uint32_t packh2(float x, float y) {
    __half2 h = __floats2half2_rn(x, y);
    return *reinterpret_cast<uint32_t*>(&h);
}

__global__ __launch_bounds__(TPB, 2)
void swin_mma_kernel(const float* __restrict__ q, const float* __restrict__ k,
                     const float* __restrict__ v, const float* __restrict__ table,
                     const int* __restrict__ index, const float* __restrict__ mask,
                     float* __restrict__ out)
{
    extern __shared__ __align__(16) char smem[];
    __half* qh  = (__half*)(smem + OFF_Q);
    __half* kh  = (__half*)(smem + OFF_K);
    __half* vth = (__half*)(smem + OFF_V);
    float*  tcol = (float*)(smem + OFF_T);

    const int t   = threadIdx.x;
    const int bh  = blockIdx.x;
    const int b   = bh >> 3, h = bh & 7;
    const int w   = b & 63;
    const size_t base = (size_t)bh * NTOK * HD;

    // ---- prologue: stage Qh, Kh (normalized fp16), Vt (fp16 transposed), tcol ----
    for (int i = t; i < TAB; i += TPB) tcol[i] = table[i * HEADS + h];
    {
        const int r = t;
        // Q
        {
            const float4* g = (const float4*)(q + base + (size_t)r * HD);
            float4 a0 = g[0], a1 = g[1], a2 = g[2], a3 = g[3];
            float ss = a0.x*a0.x+a0.y*a0.y+a0.z*a0.z+a0.w*a0.w + a1.x*a1.x+a1.y*a1.y+a1.z*a1.z+a1.w*a1.w
                     + a2.x*a2.x+a2.y*a2.y+a2.z*a2.z+a2.w*a2.w + a3.x*a3.x+a3.y*a3.y+a3.z*a3.z+a3.w*a3.w;
            float iv = rsqrtf(fmaxf(ss, 1e-24f));
            uint4 u0, u1;
            u0.x = packh2(a0.x*iv, a0.y*iv); u0.y = packh2(a0.z*iv, a0.w*iv);
            u0.z = packh2(a1.x*iv, a1.y*iv); u0.w = packh2(a1.z*iv, a1.w*iv);
            u1.x = packh2(a2.x*iv, a2.y*iv); u1.y = packh2(a2.z*iv, a2.w*iv);
            u1.z = packh2(a3.x*iv, a3.y*iv); u1.w = packh2(a3.z*iv, a3.w*iv);
            uint4* d = (uint4*)(qh + r * HD);
            d[0] = u0; d[1] = u1;
        }
        // K
        {
            const float4* g = (const float4*)(k + base + (size_t)r * HD);
            float4 a0 = g[0], a1 = g[1], a2 = g[2], a3 = g[3];
            float ss = a0.x*a0.x+a0.y*a0.y+a0.z*a0.z+a0.w*a0.w + a1.x*a1.x+a1.y*a1.y+a1.z*a1.z+a1.w*a1.w
                     + a2.x*a2.x+a2.y*a2.y+a2.z*a2.z+a2.w*a2.w + a3.x*a3.x+a3.y*a3.y+a3.z*a3.z+a3.w*a3.w;
            float iv = rsqrtf(fmaxf(ss, 1e-24f));
            uint4 u0, u1;
            u0.x = packh2(a0.x*iv, a0.y*iv); u0.y = packh2(a0.z*iv, a0.w*iv);
            u0.z = packh2(a1.x*iv, a1.y*iv); u0.w = packh2(a1.z*iv, a1.w*iv);
            u1.x = packh2(a2.x*iv, a2.y*iv); u1.y = packh2(a2.z*iv, a2.w*iv);
            u1.z = packh2(a3.x*iv, a3.y*iv); u1.w = packh2(a3.z*iv, a3.w*iv);
            uint4* d = (uint4*)(kh + r * HD);
            d[0] = u0; d[1] = u1;
        }
        // V -> Vt[d][key]
        {
            const float4* g = (const float4*)(v + base + (size_t)r * HD);
            float4 a0 = g[0], a1 = g[1], a2 = g[2], a3 = g[3];
            float vd[16] = { a0.x,a0.y,a0.z,a0.w, a1.x,a1.y,a1.z,a1.w,
                             a2.x,a2.y,a2.z,a2.w, a3.x,a3.y,a3.z,a3.w };
            #pragma unroll
            for (int d = 0; d < 16; d++) vth[d * 264 + r] = __float2half_rn(vd[d]);
        }
    }
    __syncthreads();

    // ---- warp-synchronous main loop ----
    const int wid  = t >> 5;
    const int lane = t & 31;
    const int g    = lane >> 2;     // group id (0..7)
    const int t4   = lane & 3;      // thread in group
    const int qb   = wid * 32;      // this warp's query base
    float* ABw = (float*)(smem + OFF_AB) + wid * 32 * ABSTR;

    // resident Q A-fragments (2 m-tiles)
    uint32_t qa[2][4];
    #pragma unroll
    for (int m = 0; m < 2; m++) {
        const int row = qb + m * 16 + g;
        qa[m][0] = *(const uint32_t*)(qh + row * HD + 2 * t4);
        qa[m][1] = *(const uint32_t*)(qh + (row + 8) * HD + 2 * t4);
        qa[m][2] = *(const uint32_t*)(qh + row * HD + 2 * t4 + 8);
        qa[m][3] = *(const uint32_t*)(qh + (row + 8) * HD + 2 * t4 + 8);
    }

    float o[2][2][4];
    #pragma unroll
    for (int m = 0; m < 2; m++)
        #pragma unroll
        for (int n = 0; n < 2; n++)
            #pragma unroll
            for (int i = 0; i < 4; i++) o[m][n][i] = 0.f;
    float lsum[4] = {0.f, 0.f, 0.f, 0.f};   // rows g, g+8, g+16, g+24

    const int r4 = lane >> 3;      // staging row offset (0..3)
    const int c8 = lane & 7;       // staging col group (0..7)
    const float* maskw = mask + (size_t)w * NTOK * NTOK;

    #pragma unroll 1
    for (int jb = 0; jb < 8; jb++) {
        const int j0 = jb * 32;
        __syncwarp();
        // stage bias tile ABw[32][36] = tcol[idx] + mask  (coalesced)
        #pragma unroll
        for (int it = 0; it < 8; it++) {
            const int rl = it * 4 + r4;
            const int gi = qb + rl;
            const int4   iv = *(const int4*)  (index + (size_t)gi * NTOK + j0 + c8 * 4);
            const float4 mv = *(const float4*)(maskw + (size_t)gi * NTOK + j0 + c8 * 4);
            float4 ab;
            ab.x = tcol[iv.x] + mv.x; ab.y = tcol[iv.y] + mv.y;
            ab.z = tcol[iv.z] + mv.z; ab.w = tcol[iv.w] + mv.w;
            *(float4*)(ABw + rl * ABSTR + c8 * 4) = ab;
        }
        __syncwarp();

        #pragma unroll
        for (int ks = 0; ks < 2; ks++) {        // 16 keys per k-step
            // QK: 2 n-tiles x 2 m-tiles
            float s[2][2][4];
            #pragma unroll
            for (int nl = 0; nl < 2; nl++) {
                const int key = j0 + (2 * ks + nl) * 8 + g;
                uint32_t kb[2];
                kb[0] = *(const uint32_t*)(kh + key * HD + 2 * t4);
                kb[1] = *(const uint32_t*)(kh + key * HD + 2 * t4 + 8);
                #pragma unroll
                for (int m = 0; m < 2; m++) {
                    s[nl][m][0] = s[nl][m][1] = s[nl][m][2] = s[nl][m][3] = 0.f;
                    mma16816(s[nl][m], qa[m], kb);
                }
            }
            // bias + exp -> P fragments (C layout == A layout for next mma)
            uint32_t pa[2][4];
            #pragma unroll
            for (int m = 0; m < 2; m++) {
                #pragma unroll
                for (int nl = 0; nl < 2; nl++) {
                    const int n = 2 * ks + nl;
                    const int rl = m * 16 + g;
                    float2 ab01 = *(const float2*)(ABw + rl * ABSTR + n * 8 + 2 * t4);
                    float2 ab23 = *(const float2*)(ABw + (rl + 8) * ABSTR + n * 8 + 2 * t4);
                    float p0 = __expf(s[nl][m][0] + ab01.x - SHIFT);
                    float p1 = __expf(s[nl][m][1] + ab01.y - SHIFT);
                    float p2 = __expf(s[nl][m][2] + ab23.x - SHIFT);
                    float p3 = __expf(s[nl][m][3] + ab23.y - SHIFT);
                    lsum[2 * m]     += p0 + p1;
                    lsum[2 * m + 1] += p2 + p3;
                    pa[m][nl * 2 + 0] = packh2(p0, p1);
                    pa[m][nl * 2 + 1] = packh2(p2, p3);
                }
            }
            // PV: B-frags from Vt, accumulate O
            #pragma unroll
            for (int nd = 0; nd < 2; nd++) {
                const int dim = nd * 8 + g;
                uint32_t vb[2];
                vb[0] = *(const uint32_t*)(vth + dim * 264 + j0 + ks * 16 + 2 * t4);
                vb[1] = *(const uint32_t*)(vth + dim * 264 + j0 + ks * 16 + 2 * t4 + 8);
                #pragma unroll
                for (int m = 0; m < 2; m++)
                    mma16816(o[m][nd], pa[m], vb);
            }
        }
    }

    // ---- epilogue: quad-reduce row sums, scale, store ----
    #pragma unroll
    for (int i = 0; i < 4; i++) {
        lsum[i] += __shfl_xor_sync(0xFFFFFFFF, lsum[i], 1);
        lsum[i] += __shfl_xor_sync(0xFFFFFFFF, lsum[i], 2);
    }
    float inv[4];
    #pragma unroll
    for (int i = 0; i < 4; i++) inv[i] = 1.0f / lsum[i];

    #pragma unroll
    for (int m = 0; m < 2; m++) {
        const int row = qb + m * 16 + g;
        #pragma unroll
        for (int nd = 0; nd < 2; nd++) {
            const int col = h * HD + nd * 8 + 2 * t4;
            float2 v01 = { o[m][nd][0] * inv[2 * m], o[m][nd][1] * inv[2 * m] };
            float2 v23 = { o[m][nd][2] * inv[2 * m + 1], o[m][nd][3] * inv[2 * m + 1] };
            *(float2*)(out + ((size_t)(b * NTOK + row)) * 128 + col)     = v01;
            *(float2*)(out + ((size_t)(b * NTOK + row + 8)) * 128 + col) = v23;
        }
    }
}

extern "C" void kernel_launch(void* const* d_in, const int* in_sizes, int n_in,
                              void* d_out, int out_size)
{
    const float* q     = (const float*)d_in[0];
    const float* k     = (const float*)d_in[1];
    const float* v     = (const float*)d_in[2];
    const float* table = (const float*)d_in[3];
    const int*   index = (const int*)  d_in[4];
    const float* mask  = (const float*)d_in[5];
    float* out = (float*)d_out;

    cudaFuncSetAttribute(swin_mma_kernel,
                         cudaFuncAttributeMaxDynamicSharedMemorySize, SMEM_BYTES);
    swin_mma_kernel<<<512 * HEADS, TPB, SMEM_BYTES>>>(q, k, v, table, index, mask, out);
}

// round 8
// speedup vs baseline: 4.4238x; 1.3987x over previous
#include <cuda_runtime.h>
#include <cuda_fp16.h>
#include <cstdint>

// Swin windowed attention via mma.sync.m16n8k16 + precomputed additive tile A[w,h].
// q,k,v [512,8,256,16] f32; table [961,8]; index [65536] i32; mask [64,256,256]; out [512,256,128].

#define HEADS 8
#define NTOK  256
#define HD    16
#define TAB   961
#define TPB   256
#define SHIFT 4.0f
#define NWH   512      // distinct (w,h) tiles

// scratch: bias gather (2 MB) and full additive tiles (134 MB)
__device__ float g_B[HEADS * NTOK * NTOK];          // Bh[h][ij] = table[idx,h] - SHIFT
__device__ float g_A[NWH * NTOK * NTOK];            // A[w*8+h][ij] = Bh + mask[w]

// dynamic smem layout (bytes)
#define OFF_Q   0                    // Qh [256][16] half  (8192)
#define OFF_K   8192                 // Kh [256][16] half  (8192)
#define OFF_V   16384                // Vt [16][264] half  (8448)
#define OFF_AB  24832                // ABw 8 warps x [32][40] f32 (40960)
#define ABSTR   40                   // 160 B row stride: float4-aligned, 2-way max conflicts
#define SMEM_BYTES (OFF_AB + 8*32*ABSTR*4)

static __device__ __forceinline__ void mma16816(float c[4], const uint32_t a[4], const uint32_t b[2]) {
    asm volatile("mma.sync.aligned.m16n8k16.row.col.f32.f16.f16.f32 "
                 "{%0,%1,%2,%3}, {%4,%5,%6,%7}, {%8,%9}, {%0,%1,%2,%3};"
                 : "+f"(c[0]), "+f"(c[1]), "+f"(c[2]), "+f"(c[3])
                 : "r"(a[0]), "r"(a[1]), "r"(a[2]), "r"(a[3]), "r"(b[0]), "r"(b[1]));
}
static __device__ __forceinline__ uint32_t packh2(float x, float y) {
    __half2 h = __floats2half2_rn(x, y);
    return *reinterpret_cast<uint32_t*>(&h);
}

// ---- K1: Bh[h][ij] = table[index[ij]*8 + h] - SHIFT ----
__global__ void gather_bias_kernel(const float* __restrict__ table,
                                   const int* __restrict__ index)
{
    const int ij = blockIdx.x * 256 + threadIdx.x;
    const int idx = index[ij];
    const float4* tr = (const float4*)(table + idx * HEADS);
    float4 t0 = tr[0], t1 = tr[1];
    g_B[0 * 65536 + ij] = t0.x - SHIFT;
    g_B[1 * 65536 + ij] = t0.y - SHIFT;
    g_B[2 * 65536 + ij] = t0.z - SHIFT;
    g_B[3 * 65536 + ij] = t0.w - SHIFT;
    g_B[4 * 65536 + ij] = t1.x - SHIFT;
    g_B[5 * 65536 + ij] = t1.y - SHIFT;
    g_B[6 * 65536 + ij] = t1.z - SHIFT;
    g_B[7 * 65536 + ij] = t1.w - SHIFT;
}

// ---- K2: A[w*8+h][ij] = Bh[h][ij] + mask[w][ij] ----
__global__ void combine_bias_kernel(const float* __restrict__ mask)
{
    const int wh = blockIdx.x;           // w*8 + h
    const int w = wh >> 3, h = wh & 7;
    const float4* bp = (const float4*)(g_B + h * 65536);
    const float4* mp = (const float4*)(mask + (size_t)w * 65536);
    float4* ap = (float4*)(g_A + (size_t)wh * 65536);
    // 64 iters x 256 threads x 4 floats = 65536 floats (full tile)
    #pragma unroll 8
    for (int it = 0; it < 64; it++) {
        const int e4 = it * 256 + threadIdx.x;   // float4 element index
        float4 bv = bp[e4];
        float4 mv = mp[e4];
        ap[e4] = make_float4(bv.x + mv.x, bv.y + mv.y, bv.z + mv.z, bv.w + mv.w);
    }
}

__global__ __launch_bounds__(TPB, 2)
void swin_mma_kernel(const float* __restrict__ q, const float* __restrict__ k,
                     const float* __restrict__ v, float* __restrict__ out)
{
    extern __shared__ __align__(16) char smem[];
    __half* qh  = (__half*)(smem + OFF_Q);
    __half* kh  = (__half*)(smem + OFF_K);
    __half* vth = (__half*)(smem + OFF_V);

    const int t   = threadIdx.x;
    // grid ordering: 8 images sharing (w,h) are adjacent -> A tile L2-resident
    const int bid = blockIdx.x;
    const int wh  = bid >> 3;            // 0..511 : w*8 + h
    const int img = bid & 7;
    const int w   = wh >> 3, h = wh & 7;
    const int b   = img * 64 + w;
    const int bh  = b * HEADS + h;
    const size_t base = (size_t)bh * NTOK * HD;
    const float* Aw = g_A + (size_t)wh * 65536;

    // ---- prologue: stage Qh, Kh (normalized fp16), Vt (fp16 transposed) ----
    {
        const int r = t;
        // Q
        {
            const float4* g = (const float4*)(q + base + (size_t)r * HD);
            float4 a0 = g[0], a1 = g[1], a2 = g[2], a3 = g[3];
            float ss = a0.x*a0.x+a0.y*a0.y+a0.z*a0.z+a0.w*a0.w + a1.x*a1.x+a1.y*a1.y+a1.z*a1.z+a1.w*a1.w
                     + a2.x*a2.x+a2.y*a2.y+a2.z*a2.z+a2.w*a2.w + a3.x*a3.x+a3.y*a3.y+a3.z*a3.z+a3.w*a3.w;
            float iv = rsqrtf(fmaxf(ss, 1e-24f));
            uint4 u0, u1;
            u0.x = packh2(a0.x*iv, a0.y*iv); u0.y = packh2(a0.z*iv, a0.w*iv);
            u0.z = packh2(a1.x*iv, a1.y*iv); u0.w = packh2(a1.z*iv, a1.w*iv);
            u1.x = packh2(a2.x*iv, a2.y*iv); u1.y = packh2(a2.z*iv, a2.w*iv);
            u1.z = packh2(a3.x*iv, a3.y*iv); u1.w = packh2(a3.z*iv, a3.w*iv);
            uint4* d = (uint4*)(qh + r * HD);
            d[0] = u0; d[1] = u1;
        }
        // K
        {
            const float4* g = (const float4*)(k + base + (size_t)r * HD);
            float4 a0 = g[0], a1 = g[1], a2 = g[2], a3 = g[3];
            float ss = a0.x*a0.x+a0.y*a0.y+a0.z*a0.z+a0.w*a0.w + a1.x*a1.x+a1.y*a1.y+a1.z*a1.z+a1.w*a1.w
                     + a2.x*a2.x+a2.y*a2.y+a2.z*a2.z+a2.w*a2.w + a3.x*a3.x+a3.y*a3.y+a3.z*a3.z+a3.w*a3.w;
            float iv = rsqrtf(fmaxf(ss, 1e-24f));
            uint4 u0, u1;
            u0.x = packh2(a0.x*iv, a0.y*iv); u0.y = packh2(a0.z*iv, a0.w*iv);
            u0.z = packh2(a1.x*iv, a1.y*iv); u0.w = packh2(a1.z*iv, a1.w*iv);
            u1.x = packh2(a2.x*iv, a2.y*iv); u1.y = packh2(a2.z*iv, a2.w*iv);
            u1.z = packh2(a3.x*iv, a3.y*iv); u1.w = packh2(a3.z*iv, a3.w*iv);
            uint4* d = (uint4*)(kh + r * HD);
            d[0] = u0; d[1] = u1;
        }
        // V -> Vt[d][key]
        {
            const float4* g = (const float4*)(v + base + (size_t)r * HD);
            float4 a0 = g[0], a1 = g[1], a2 = g[2], a3 = g[3];
            float vd[16] = { a0.x,a0.y,a0.z,a0.w, a1.x,a1.y,a1.z,a1.w,
                             a2.x,a2.y,a2.z,a2.w, a3.x,a3.y,a3.z,a3.w };
            #pragma unroll
            for (int d = 0; d < 16; d++) vth[d * 264 + r] = __float2half_rn(vd[d]);
        }
    }
    __syncthreads();

    // ---- warp-synchronous main loop ----
    const int wid  = t >> 5;
    const int lane = t & 31;
    const int g    = lane >> 2;
    const int t4   = lane & 3;
    const int qb   = wid * 32;
    float* ABw = (float*)(smem + OFF_AB) + wid * 32 * ABSTR;

    uint32_t qa[2][4];
    #pragma unroll
    for (int m = 0; m < 2; m++) {
        const int row = qb + m * 16 + g;
        qa[m][0] = *(const uint32_t*)(qh + row * HD + 2 * t4);
        qa[m][1] = *(const uint32_t*)(qh + (row + 8) * HD + 2 * t4);
        qa[m][2] = *(const uint32_t*)(qh + row * HD + 2 * t4 + 8);
        qa[m][3] = *(const uint32_t*)(qh + (row + 8) * HD + 2 * t4 + 8);
    }

    float o[2][2][4];
    #pragma unroll
    for (int m = 0; m < 2; m++)
        #pragma unroll
        for (int n = 0; n < 2; n++)
            #pragma unroll
            for (int i = 0; i < 4; i++) o[m][n][i] = 0.f;
    float lsum[4] = {0.f, 0.f, 0.f, 0.f};

    const int r4 = lane >> 3;
    const int c8 = lane & 7;

    #pragma unroll 1
    for (int jb = 0; jb < 8; jb++) {
        const int j0 = jb * 32;
        __syncwarp();
        // stage additive tile: single coalesced LDG stream (gather already folded)
        #pragma unroll
        for (int it = 0; it < 8; it++) {
            const int rl = it * 4 + r4;
            const int gi = qb + rl;
            float4 av = *(const float4*)(Aw + gi * NTOK + j0 + c8 * 4);
            *(float4*)(ABw + rl * ABSTR + c8 * 4) = av;
        }
        __syncwarp();

        #pragma unroll
        for (int ks = 0; ks < 2; ks++) {
            float s[2][2][4];
            #pragma unroll
            for (int nl = 0; nl < 2; nl++) {
                const int key = j0 + (2 * ks + nl) * 8 + g;
                uint32_t kb[2];
                kb[0] = *(const uint32_t*)(kh + key * HD + 2 * t4);
                kb[1] = *(const uint32_t*)(kh + key * HD + 2 * t4 + 8);
                #pragma unroll
                for (int m = 0; m < 2; m++) {
                    s[nl][m][0] = s[nl][m][1] = s[nl][m][2] = s[nl][m][3] = 0.f;
                    mma16816(s[nl][m], qa[m], kb);
                }
            }
            uint32_t pa[2][4];
            #pragma unroll
            for (int m = 0; m < 2; m++) {
                #pragma unroll
                for (int nl = 0; nl < 2; nl++) {
                    const int n = 2 * ks + nl;
                    const int rl = m * 16 + g;
                    float2 ab01 = *(const float2*)(ABw + rl * ABSTR + n * 8 + 2 * t4);
                    float2 ab23 = *(const float2*)(ABw + (rl + 8) * ABSTR + n * 8 + 2 * t4);
                    float p0 = __expf(s[nl][m][0] + ab01.x);
                    float p1 = __expf(s[nl][m][1] + ab01.y);
                    float p2 = __expf(s[nl][m][2] + ab23.x);
                    float p3 = __expf(s[nl][m][3] + ab23.y);
                    lsum[2 * m]     += p0 + p1;
                    lsum[2 * m + 1] += p2 + p3;
                    pa[m][nl * 2 + 0] = packh2(p0, p1);
                    pa[m][nl * 2 + 1] = packh2(p2, p3);
                }
            }
            #pragma unroll
            for (int nd = 0; nd < 2; nd++) {
                const int dim = nd * 8 + g;
                uint32_t vb[2];
                vb[0] = *(const uint32_t*)(vth + dim * 264 + j0 + ks * 16 + 2 * t4);
                vb[1] = *(const uint32_t*)(vth + dim * 264 + j0 + ks * 16 + 2 * t4 + 8);
                #pragma unroll
                for (int m = 0; m < 2; m++)
                    mma16816(o[m][nd], pa[m], vb);
            }
        }
    }

    // ---- epilogue ----
    #pragma unroll
    for (int i = 0; i < 4; i++) {
        lsum[i] += __shfl_xor_sync(0xFFFFFFFF, lsum[i], 1);
        lsum[i] += __shfl_xor_sync(0xFFFFFFFF, lsum[i], 2);
    }
    float inv[4];
    #pragma unroll
    for (int i = 0; i < 4; i++) inv[i] = 1.0f / lsum[i];

    #pragma unroll
    for (int m = 0; m < 2; m++) {
        const int row = qb + m * 16 + g;
        #pragma unroll
        for (int nd = 0; nd < 2; nd++) {
            const int col = h * HD + nd * 8 + 2 * t4;
            float2 v01 = { o[m][nd][0] * inv[2 * m], o[m][nd][1] * inv[2 * m] };
            float2 v23 = { o[m][nd][2] * inv[2 * m + 1], o[m][nd][3] * inv[2 * m + 1] };
            *(float2*)(out + ((size_t)(b * NTOK + row)) * 128 + col)     = v01;
            *(float2*)(out + ((size_t)(b * NTOK + row + 8)) * 128 + col) = v23;
        }
    }
}

extern "C" void kernel_launch(void* const* d_in, const int* in_sizes, int n_in,
                              void* d_out, int out_size)
{
    const float* q     = (const float*)d_in[0];
    const float* k     = (const float*)d_in[1];
    const float* v     = (const float*)d_in[2];
    const float* table = (const float*)d_in[3];
    const int*   index = (const int*)  d_in[4];
    const float* mask  = (const float*)d_in[5];
    float* out = (float*)d_out;

    gather_bias_kernel<<<256, 256>>>(table, index);
    combine_bias_kernel<<<NWH, 256>>>(mask);

    cudaFuncSetAttribute(swin_mma_kernel,
                         cudaFuncAttributeMaxDynamicSharedMemorySize, SMEM_BYTES);
    swin_mma_kernel<<<4096, TPB, SMEM_BYTES>>>(q, k, v, out);
}

// round 10
// speedup vs baseline: 5.2967x; 1.1973x over previous
#include <cuda_runtime.h>
#include <cuda_fp16.h>
#include <cstdint>

// Swin windowed attention: HMMA m16n8k16 + precomputed E[w,h] = exp(bias+mask-SHIFT) in fp16.
// q,k,v [512,8,256,16] f32; table [961,8]; index [65536] i32; mask [64,256,256]; out [512,256,128].

#define HEADS 8
#define NTOK  256
#define HD    16
#define TAB   961
#define TPB   256
#define SHIFT 4.0f
#define NWH   512      // distinct (w,h) tiles

// scratch: bias gather (2 MB) and exp-tiles (67 MB, fp16)
__device__ float  g_B[HEADS * NTOK * NTOK];   // Bh[h][ij] = table[idx,h] - SHIFT
__device__ __half g_E[NWH * NTOK * NTOK];     // E[w*8+h][ij] = exp(Bh + mask[w])

// dynamic smem layout (bytes)
#define OFF_Q   0                    // Qh [256][16] half  (8192)
#define OFF_K   8192                 // Kh [256][16] half  (8192)
#define OFF_V   16384                // Vt [16][264] half  (8448)
#define OFF_EB  24832                // EBw 8 warps x [32][72] half (36864)
#define EBSTR   72                   // 144 B row stride: 16B-aligned, conflict-free frag reads
#define SMEM_BYTES (OFF_EB + 8*32*EBSTR*2)

static __device__ __forceinline__ void mma16816(float c[4], const uint32_t a[4], const uint32_t b[2]) {
    asm volatile("mma.sync.aligned.m16n8k16.row.col.f32.f16.f16.f32 "
                 "{%0,%1,%2,%3}, {%4,%5,%6,%7}, {%8,%9}, {%0,%1,%2,%3};"
                 : "+f"(c[0]), "+f"(c[1]), "+f"(c[2]), "+f"(c[3])
                 : "r"(a[0]), "r"(a[1]), "r"(a[2]), "r"(a[3]), "r"(b[0]), "r"(b[1]));
}
static __device__ __forceinline__ uint32_t packh2(float x, float y) {
    __half2 h = __floats2half2_rn(x, y);
    return *reinterpret_cast<uint32_t*>(&h);
}

// ---- K1: Bh[h][ij] = table[index[ij]*8 + h] - SHIFT ----
__global__ void gather_bias_kernel(const float* __restrict__ table,
                                   const int* __restrict__ index)
{
    const int ij = blockIdx.x * 256 + threadIdx.x;
    const int idx = index[ij];
    const float4* tr = (const float4*)(table + idx * HEADS);
    float4 t0 = tr[0], t1 = tr[1];
    g_B[0 * 65536 + ij] = t0.x - SHIFT;
    g_B[1 * 65536 + ij] = t0.y - SHIFT;
    g_B[2 * 65536 + ij] = t0.z - SHIFT;
    g_B[3 * 65536 + ij] = t0.w - SHIFT;
    g_B[4 * 65536 + ij] = t1.x - SHIFT;
    g_B[5 * 65536 + ij] = t1.y - SHIFT;
    g_B[6 * 65536 + ij] = t1.z - SHIFT;
    g_B[7 * 65536 + ij] = t1.w - SHIFT;
}

// ---- K2: E[w*8+h][ij] = exp(Bh[h][ij] + mask[w][ij])  (fp16) ----
__global__ void combine_exp_kernel(const float* __restrict__ mask)
{
    const int wh = blockIdx.x;           // w*8 + h
    const int w = wh >> 3, h = wh & 7;
    const float4* bp = (const float4*)(g_B + h * 65536);
    const float4* mp = (const float4*)(mask + (size_t)w * 65536);
    uint2* ep = (uint2*)(g_E + (size_t)wh * 65536);
    #pragma unroll 8
    for (int it = 0; it < 64; it++) {
        const int e4 = it * 256 + threadIdx.x;   // group of 4 elements
        float4 bv = bp[e4];
        float4 mv = mp[e4];
        uint2 o;
        o.x = packh2(__expf(bv.x + mv.x), __expf(bv.y + mv.y));
        o.y = packh2(__expf(bv.z + mv.z), __expf(bv.w + mv.w));
        ep[e4] = o;
    }
}

__global__ __launch_bounds__(TPB, 2)
void swin_mma_kernel(const float* __restrict__ q, const float* __restrict__ k,
                     const float* __restrict__ v, float* __restrict__ out)
{
    extern __shared__ __align__(16) char smem[];
    __half* qh  = (__half*)(smem + OFF_Q);
    __half* kh  = (__half*)(smem + OFF_K);
    __half* vth = (__half*)(smem + OFF_V);

    const int t   = threadIdx.x;
    // grid ordering: 8 images sharing (w,h) are adjacent -> E tile L2-resident
    const int bid = blockIdx.x;
    const int wh  = bid >> 3;            // 0..511 : w*8 + h
    const int img = bid & 7;
    const int w   = wh >> 3, h = wh & 7;
    const int b   = img * 64 + w;
    const int bh  = b * HEADS + h;
    const size_t base = (size_t)bh * NTOK * HD;
    const __half* Ew = g_E + (size_t)wh * 65536;

    // ---- prologue: stage Qh, Kh (normalized fp16), Vt (fp16 transposed) ----
    {
        const int r = t;
        // Q
        {
            const float4* g = (const float4*)(q + base + (size_t)r * HD);
            float4 a0 = g[0], a1 = g[1], a2 = g[2], a3 = g[3];
            float ss = a0.x*a0.x+a0.y*a0.y+a0.z*a0.z+a0.w*a0.w + a1.x*a1.x+a1.y*a1.y+a1.z*a1.z+a1.w*a1.w
                     + a2.x*a2.x+a2.y*a2.y+a2.z*a2.z+a2.w*a2.w + a3.x*a3.x+a3.y*a3.y+a3.z*a3.z+a3.w*a3.w;
            float iv = rsqrtf(fmaxf(ss, 1e-24f));
            uint4 u0, u1;
            u0.x = packh2(a0.x*iv, a0.y*iv); u0.y = packh2(a0.z*iv, a0.w*iv);
            u0.z = packh2(a1.x*iv, a1.y*iv); u0.w = packh2(a1.z*iv, a1.w*iv);
            u1.x = packh2(a2.x*iv, a2.y*iv); u1.y = packh2(a2.z*iv, a2.w*iv);
            u1.z = packh2(a3.x*iv, a3.y*iv); u1.w = packh2(a3.z*iv, a3.w*iv);
            uint4* d = (uint4*)(qh + r * HD);
            d[0] = u0; d[1] = u1;
        }
        // K
        {
            const float4* g = (const float4*)(k + base + (size_t)r * HD);
            float4 a0 = g[0], a1 = g[1], a2 = g[2], a3 = g[3];
            float ss = a0.x*a0.x+a0.y*a0.y+a0.z*a0.z+a0.w*a0.w + a1.x*a1.x+a1.y*a1.y+a1.z*a1.z+a1.w*a1.w
                     + a2.x*a2.x+a2.y*a2.y+a2.z*a2.z+a2.w*a2.w + a3.x*a3.x+a3.y*a3.y+a3.z*a3.z+a3.w*a3.w;
            float iv = rsqrtf(fmaxf(ss, 1e-24f));
            uint4 u0, u1;
            u0.x = packh2(a0.x*iv, a0.y*iv); u0.y = packh2(a0.z*iv, a0.w*iv);
            u0.z = packh2(a1.x*iv, a1.y*iv); u0.w = packh2(a1.z*iv, a1.w*iv);
            u1.x = packh2(a2.x*iv, a2.y*iv); u1.y = packh2(a2.z*iv, a2.w*iv);
            u1.z = packh2(a3.x*iv, a3.y*iv); u1.w = packh2(a3.z*iv, a3.w*iv);
            uint4* d = (uint4*)(kh + r * HD);
            d[0] = u0; d[1] = u1;
        }
        // V -> Vt[d][key]
        {
            const float4* g = (const float4*)(v + base + (size_t)r * HD);
            float4 a0 = g[0], a1 = g[1], a2 = g[2], a3 = g[3];
            float vd[16] = { a0.x,a0.y,a0.z,a0.w, a1.x,a1.y,a1.z,a1.w,
                             a2.x,a2.y,a2.z,a2.w, a3.x,a3.y,a3.z,a3.w };
            #pragma unroll
            for (int d = 0; d < 16; d++) vth[d * 264 + r] = __float2half_rn(vd[d]);
        }
    }
    __syncthreads();

    // ---- warp-synchronous main loop ----
    const int wid  = t >> 5;
    const int lane = t & 31;
    const int g    = lane >> 2;
    const int t4   = lane & 3;
    const int qb   = wid * 32;
    __half* EBw = (__half*)(smem + OFF_EB) + wid * 32 * EBSTR;

    uint32_t qa[2][4];
    #pragma unroll
    for (int m = 0; m < 2; m++) {
        const int row = qb + m * 16 + g;
        qa[m][0] = *(const uint32_t*)(qh + row * HD + 2 * t4);
        qa[m][1] = *(const uint32_t*)(qh + (row + 8) * HD + 2 * t4);
        qa[m][2] = *(const uint32_t*)(qh + row * HD + 2 * t4 + 8);
        qa[m][3] = *(const uint32_t*)(qh + (row + 8) * HD + 2 * t4 + 8);
    }

    float o[2][2][4];
    #pragma unroll
    for (int m = 0; m < 2; m++)
        #pragma unroll
        for (int n = 0; n < 2; n++)
            #pragma unroll
            for (int i = 0; i < 4; i++) o[m][n][i] = 0.f;
    float lsum[4] = {0.f, 0.f, 0.f, 0.f};

    const int r8 = lane >> 3;     // staging row (0..3)
    const int c8 = lane & 7;      // staging 16B chunk (0..7)

    #pragma unroll 1
    for (int jb = 0; jb < 4; jb++) {          // 64 keys per block
        const int j0 = jb * 64;
        __syncwarp();
        // stage E tile [32 rows][64 keys] fp16: full-line LDG.128, aligned STS.128
        #pragma unroll
        for (int it = 0; it < 8; it++) {
            const int rl = it * 4 + r8;
            const int gi = qb + rl;
            uint4 ev = *(const uint4*)(Ew + gi * NTOK + j0 + c8 * 8);
            *(uint4*)(EBw + rl * EBSTR + c8 * 8) = ev;
        }
        __syncwarp();

        #pragma unroll
        for (int kk = 0; kk < 4; kk++) {      // 16 keys per k-step
            float s[2][2][4];
            #pragma unroll
            for (int nl = 0; nl < 2; nl++) {
                const int key = j0 + kk * 16 + nl * 8 + g;
                uint32_t kb[2];
                kb[0] = *(const uint32_t*)(kh + key * HD + 2 * t4);
                kb[1] = *(const uint32_t*)(kh + key * HD + 2 * t4 + 8);
                #pragma unroll
                for (int m = 0; m < 2; m++) {
                    s[nl][m][0] = s[nl][m][1] = s[nl][m][2] = s[nl][m][3] = 0.f;
                    mma16816(s[nl][m], qa[m], kb);
                }
            }
            uint32_t pa[2][4];
            #pragma unroll
            for (int m = 0; m < 2; m++) {
                #pragma unroll
                for (int nl = 0; nl < 2; nl++) {
                    const int nloc = kk * 2 + nl;          // 0..7 within 64-key tile
                    const int rl = m * 16 + g;
                    const int col = nloc * 8 + 2 * t4;
                    __half2 e01h = *(const __half2*)(EBw + rl * EBSTR + col);
                    __half2 e23h = *(const __half2*)(EBw + (rl + 8) * EBSTR + col);
                    float2 e01 = __half22float2(e01h);
                    float2 e23 = __half22float2(e23h);
                    float p0 = __expf(s[nl][m][0]) * e01.x;
                    float p1 = __expf(s[nl][m][1]) * e01.y;
                    float p2 = __expf(s[nl][m][2]) * e23.x;
                    float p3 = __expf(s[nl][m][3]) * e23.y;
                    lsum[2 * m]     += p0 + p1;
                    lsum[2 * m + 1] += p2 + p3;
                    pa[m][nl * 2 + 0] = packh2(p0, p1);
                    pa[m][nl * 2 + 1] = packh2(p2, p3);
                }
            }
            #pragma unroll
            for (int nd = 0; nd < 2; nd++) {
                const int dim = nd * 8 + g;
                uint32_t vb[2];
                vb[0] = *(const uint32_t*)(vth + dim * 264 + j0 + kk * 16 + 2 * t4);
                vb[1] = *(const uint32_t*)(vth + dim * 264 + j0 + kk * 16 + 2 * t4 + 8);
                #pragma unroll
                for (int m = 0; m < 2; m++)
                    mma16816(o[m][nd], pa[m], vb);
            }
        }
    }

    // ---- epilogue ----
    #pragma unroll
    for (int i = 0; i < 4; i++) {
        lsum[i] += __shfl_xor_sync(0xFFFFFFFF, lsum[i], 1);
        lsum[i] += __shfl_xor_sync(0xFFFFFFFF, lsum[i], 2);
    }
    float inv[4];
    #pragma unroll
    for (int i = 0; i < 4; i++) inv[i] = 1.0f / lsum[i];

    #pragma unroll
    for (int m = 0; m < 2; m++) {
        const int row = qb + m * 16 + g;
        #pragma unroll
        for (int nd = 0; nd < 2; nd++) {
            const int col = h * HD + nd * 8 + 2 * t4;
            float2 v01 = { o[m][nd][0] * inv[2 * m], o[m][nd][1] * inv[2 * m] };
            float2 v23 = { o[m][nd][2] * inv[2 * m + 1], o[m][nd][3] * inv[2 * m + 1] };
            *(float2*)(out + ((size_t)(b * NTOK + row)) * 128 + col)     = v01;
            *(float2*)(out + ((size_t)(b * NTOK + row + 8)) * 128 + col) = v23;
        }
    }
}

extern "C" void kernel_launch(void* const* d_in, const int* in_sizes, int n_in,
                              void* d_out, int out_size)
{
    const float* q     = (const float*)d_in[0];
    const float* k     = (const float*)d_in[1];
    const float* v     = (const float*)d_in[2];
    const float* table = (const float*)d_in[3];
    const int*   index = (const int*)  d_in[4];
    const float* mask  = (const float*)d_in[5];
    float* out = (float*)d_out;

    gather_bias_kernel<<<256, 256>>>(table, index);
    combine_exp_kernel<<<NWH, 256>>>(mask);

    cudaFuncSetAttribute(swin_mma_kernel,
                         cudaFuncAttributeMaxDynamicSharedMemorySize, SMEM_BYTES);
    swin_mma_kernel<<<4096, TPB, SMEM_BYTES>>>(q, k, v, out);
}

// round 11
// speedup vs baseline: 5.3716x; 1.0141x over previous
#include <cuda_runtime.h>
#include <cuda_fp16.h>
#include <cstdint>

// Swin windowed attention: HMMA m16n8k16, precomputed E[w,h]=exp(bias+mask-SHIFT) fp16,
// half2 softmax via EX2.f16x2 (log2e folded into Q), lsum via ones-column PV MMA.

#define HEADS 8
#define NTOK  256
#define HD    16
#define TAB   961
#define TPB   256
#define SHIFT 4.0f
#define NWH   512
#define LOG2E 1.44269504f

__device__ float  g_B[HEADS * NTOK * NTOK];   // Bh[h][ij] = table[idx,h] - SHIFT
__device__ __half g_E[NWH * NTOK * NTOK];     // E[w*8+h][ij] = exp(Bh + mask[w])

// dynamic smem layout (bytes)
#define OFF_Q   0                    // Qh [256][16] half  (8192)
#define OFF_K   8192                 // Kh [256][16] half  (8192)
#define OFF_V   16384                // Vt [24][264] half  (12672) ; row16 = ones
#define OFF_EB  29056                // EBw 8 warps x [32][72] half (36864)
#define EBSTR   72
#define SMEM_BYTES (OFF_EB + 8*32*EBSTR*2)

static __device__ __forceinline__ void mma16816(float c[4], const uint32_t a[4], const uint32_t b[2]) {
    asm volatile("mma.sync.aligned.m16n8k16.row.col.f32.f16.f16.f32 "
                 "{%0,%1,%2,%3}, {%4,%5,%6,%7}, {%8,%9}, {%0,%1,%2,%3};"
                 : "+f"(c[0]), "+f"(c[1]), "+f"(c[2]), "+f"(c[3])
                 : "r"(a[0]), "r"(a[1]), "r"(a[2]), "r"(a[3]), "r"(b[0]), "r"(b[1]));
}
static __device__ __forceinline__ uint32_t packh2(float x, float y) {
    __half2 h = __floats2half2_rn(x, y);
    return *reinterpret_cast<uint32_t*>(&h);
}

// ---- K1: Bh[h][ij] = table[index[ij]*8 + h] - SHIFT ----
__global__ void gather_bias_kernel(const float* __restrict__ table,
                                   const int* __restrict__ index)
{
    const int ij = blockIdx.x * 256 + threadIdx.x;
    const int idx = index[ij];
    const float4* tr = (const float4*)(table + idx * HEADS);
    float4 t0 = tr[0], t1 = tr[1];
    g_B[0 * 65536 + ij] = t0.x - SHIFT;
    g_B[1 * 65536 + ij] = t0.y - SHIFT;
    g_B[2 * 65536 + ij] = t0.z - SHIFT;
    g_B[3 * 65536 + ij] = t0.w - SHIFT;
    g_B[4 * 65536 + ij] = t1.x - SHIFT;
    g_B[5 * 65536 + ij] = t1.y - SHIFT;
    g_B[6 * 65536 + ij] = t1.z - SHIFT;
    g_B[7 * 65536 + ij] = t1.w - SHIFT;
}

// ---- K2: E[w*8+h][ij] = exp(Bh[h][ij] + mask[w][ij])  (fp16) ----
__global__ void combine_exp_kernel(const float* __restrict__ mask)
{
    const int wh = blockIdx.x;
    const int w = wh >> 3, h = wh & 7;
    const float4* bp = (const float4*)(g_B + h * 65536);
    const float4* mp = (const float4*)(mask + (size_t)w * 65536);
    uint2* ep = (uint2*)(g_E + (size_t)wh * 65536);
    #pragma unroll 8
    for (int it = 0; it < 64; it++) {
        const int e4 = it * 256 + threadIdx.x;
        float4 bv = bp[e4];
        float4 mv = mp[e4];
        uint2 o;
        o.x = packh2(__expf(bv.x + mv.x), __expf(bv.y + mv.y));
        o.y = packh2(__expf(bv.z + mv.z), __expf(bv.w + mv.w));
        ep[e4] = o;
    }
}

__global__ __launch_bounds__(TPB, 2)
void swin_mma_kernel(const float* __restrict__ q, const float* __restrict__ k,
                     const float* __restrict__ v, float* __restrict__ out)
{
    extern __shared__ __align__(16) char smem[];
    __half* qh  = (__half*)(smem + OFF_Q);
    __half* kh  = (__half*)(smem + OFF_K);
    __half* vth = (__half*)(smem + OFF_V);

    const int t   = threadIdx.x;
    const int bid = blockIdx.x;
    const int wh  = bid >> 3;            // 8 images sharing (w,h) adjacent -> E L2-resident
    const int img = bid & 7;
    const int w   = wh >> 3, h = wh & 7;
    const int b   = img * 64 + w;
    const int bh  = b * HEADS + h;
    const size_t base = (size_t)bh * NTOK * HD;
    const __half* Ew = g_E + (size_t)wh * 65536;

    // ---- prologue ----
    {
        const int r = t;
        // Q: normalized * log2e (folds exp base conversion into the MMA)
        {
            const float4* g = (const float4*)(q + base + (size_t)r * HD);
            float4 a0 = g[0], a1 = g[1], a2 = g[2], a3 = g[3];
            float ss = a0.x*a0.x+a0.y*a0.y+a0.z*a0.z+a0.w*a0.w + a1.x*a1.x+a1.y*a1.y+a1.z*a1.z+a1.w*a1.w
                     + a2.x*a2.x+a2.y*a2.y+a2.z*a2.z+a2.w*a2.w + a3.x*a3.x+a3.y*a3.y+a3.z*a3.z+a3.w*a3.w;
            float iv = rsqrtf(fmaxf(ss, 1e-24f)) * LOG2E;
            uint4 u0, u1;
            u0.x = packh2(a0.x*iv, a0.y*iv); u0.y = packh2(a0.z*iv, a0.w*iv);
            u0.z = packh2(a1.x*iv, a1.y*iv); u0.w = packh2(a1.z*iv, a1.w*iv);
            u1.x = packh2(a2.x*iv, a2.y*iv); u1.y = packh2(a2.z*iv, a2.w*iv);
            u1.z = packh2(a3.x*iv, a3.y*iv); u1.w = packh2(a3.z*iv, a3.w*iv);
            uint4* d = (uint4*)(qh + r * HD);
            d[0] = u0; d[1] = u1;
        }
        // K normalized
        {
            const float4* g = (const float4*)(k + base + (size_t)r * HD);
            float4 a0 = g[0], a1 = g[1], a2 = g[2], a3 = g[3];
            float ss = a0.x*a0.x+a0.y*a0.y+a0.z*a0.z+a0.w*a0.w + a1.x*a1.x+a1.y*a1.y+a1.z*a1.z+a1.w*a1.w
                     + a2.x*a2.x+a2.y*a2.y+a2.z*a2.z+a2.w*a2.w + a3.x*a3.x+a3.y*a3.y+a3.z*a3.z+a3.w*a3.w;
            float iv = rsqrtf(fmaxf(ss, 1e-24f));
            uint4 u0, u1;
            u0.x = packh2(a0.x*iv, a0.y*iv); u0.y = packh2(a0.z*iv, a0.w*iv);
            u0.z = packh2(a1.x*iv, a1.y*iv); u0.w = packh2(a1.z*iv, a1.w*iv);
            u1.x = packh2(a2.x*iv, a2.y*iv); u1.y = packh2(a2.z*iv, a2.w*iv);
            u1.z = packh2(a3.x*iv, a3.y*iv); u1.w = packh2(a3.z*iv, a3.w*iv);
            uint4* d = (uint4*)(kh + r * HD);
            d[0] = u0; d[1] = u1;
        }
        // V -> Vt[d][key], rows 16..23: row16 = ones (lsum column), rest zero
        {
            const float4* g = (const float4*)(v + base + (size_t)r * HD);
            float4 a0 = g[0], a1 = g[1], a2 = g[2], a3 = g[3];
            float vd[16] = { a0.x,a0.y,a0.z,a0.w, a1.x,a1.y,a1.z,a1.w,
                             a2.x,a2.y,a2.z,a2.w, a3.x,a3.y,a3.z,a3.w };
            #pragma unroll
            for (int d = 0; d < 16; d++) vth[d * 264 + r] = __float2half_rn(vd[d]);
        }
        for (int i = t; i < 8 * 264; i += TPB) {
            const int row = 16 + i / 264, col = i % 264;
            vth[row * 264 + col] = (row == 16 && col < 256) ? __float2half_rn(1.0f)
                                                            : __float2half_rn(0.0f);
        }
    }
    __syncthreads();

    // ---- warp-synchronous main loop ----
    const int wid  = t >> 5;
    const int lane = t & 31;
    const int g    = lane >> 2;
    const int t4   = lane & 3;
    const int qb   = wid * 32;
    __half* EBw = (__half*)(smem + OFF_EB) + wid * 32 * EBSTR;

    uint32_t qa[2][4];
    #pragma unroll
    for (int m = 0; m < 2; m++) {
        const int row = qb + m * 16 + g;
        qa[m][0] = *(const uint32_t*)(qh + row * HD + 2 * t4);
        qa[m][1] = *(const uint32_t*)(qh + (row + 8) * HD + 2 * t4);
        qa[m][2] = *(const uint32_t*)(qh + row * HD + 2 * t4 + 8);
        qa[m][3] = *(const uint32_t*)(qh + (row + 8) * HD + 2 * t4 + 8);
    }

    float o[2][3][4];   // nd=2 is the lsum (ones) tile
    #pragma unroll
    for (int m = 0; m < 2; m++)
        #pragma unroll
        for (int n = 0; n < 3; n++)
            #pragma unroll
            for (int i = 0; i < 4; i++) o[m][n][i] = 0.f;

    const int r8 = lane >> 3;
    const int c8 = lane & 7;

    #pragma unroll 1
    for (int jb = 0; jb < 4; jb++) {          // 64 keys per block
        const int j0 = jb * 64;
        __syncwarp();
        #pragma unroll
        for (int it = 0; it < 8; it++) {
            const int rl = it * 4 + r8;
            const int gi = qb + rl;
            uint4 ev = *(const uint4*)(Ew + gi * NTOK + j0 + c8 * 8);
            *(uint4*)(EBw + rl * EBSTR + c8 * 8) = ev;
        }
        __syncwarp();

        #pragma unroll
        for (int kk = 0; kk < 4; kk++) {      // 16 keys per k-step
            float s[2][2][4];
            #pragma unroll
            for (int nl = 0; nl < 2; nl++) {
                const int key = j0 + kk * 16 + nl * 8 + g;
                uint32_t kb[2];
                kb[0] = *(const uint32_t*)(kh + key * HD + 2 * t4);
                kb[1] = *(const uint32_t*)(kh + key * HD + 2 * t4 + 8);
                #pragma unroll
                for (int m = 0; m < 2; m++) {
                    s[nl][m][0] = s[nl][m][1] = s[nl][m][2] = s[nl][m][3] = 0.f;
                    mma16816(s[nl][m], qa[m], kb);
                }
            }
            // half2 softmax: p = 2^s * E   (s already includes log2e factor)
            uint32_t pa[2][4];
            #pragma unroll
            for (int m = 0; m < 2; m++) {
                #pragma unroll
                for (int nl = 0; nl < 2; nl++) {
                    const int nloc = kk * 2 + nl;
                    const int rl = m * 16 + g;
                    const int col = nloc * 8 + 2 * t4;
                    __half2 e01 = *(const __half2*)(EBw + rl * EBSTR + col);
                    __half2 e23 = *(const __half2*)(EBw + (rl + 8) * EBSTR + col);
                    __half2 s01 = __floats2half2_rn(s[nl][m][0], s[nl][m][1]);
                    __half2 s23 = __floats2half2_rn(s[nl][m][2], s[nl][m][3]);
                    __half2 p01 = __hmul2(h2exp2(s01), e01);
                    __half2 p23 = __hmul2(h2exp2(s23), e23);
                    pa[m][nl * 2 + 0] = *reinterpret_cast<uint32_t*>(&p01);
                    pa[m][nl * 2 + 1] = *reinterpret_cast<uint32_t*>(&p23);
                }
            }
            // PV + lsum: 3 n-tiles (dims 0-7, 8-15, ones@16)
            #pragma unroll
            for (int nd = 0; nd < 3; nd++) {
                const int dim = nd * 8 + g;
                uint32_t vb[2];
                vb[0] = *(const uint32_t*)(vth + dim * 264 + j0 + kk * 16 + 2 * t4);
                vb[1] = *(const uint32_t*)(vth + dim * 264 + j0 + kk * 16 + 2 * t4 + 8);
                #pragma unroll
                for (int m = 0; m < 2; m++)
                    mma16816(o[m][nd], pa[m], vb);
            }
        }
    }

    // ---- epilogue: lsum lives in ones-column (col16, held by t4==0 as c0/c2) ----
    #pragma unroll
    for (int m = 0; m < 2; m++) {
        const float l0 = __shfl_sync(0xFFFFFFFF, o[m][2][0], lane & ~3);
        const float l1 = __shfl_sync(0xFFFFFFFF, o[m][2][2], lane & ~3);
        const float inv0 = 1.0f / l0;
        const float inv1 = 1.0f / l1;
        const int row = qb + m * 16 + g;
        #pragma unroll
        for (int nd = 0; nd < 2; nd++) {
            const int col = h * HD + nd * 8 + 2 * t4;
            float2 v01 = { o[m][nd][0] * inv0, o[m][nd][1] * inv0 };
            float2 v23 = { o[m][nd][2] * inv1, o[m][nd][3] * inv1 };
            *(float2*)(out + ((size_t)(b * NTOK + row)) * 128 + col)     = v01;
            *(float2*)(out + ((size_t)(b * NTOK + row + 8)) * 128 + col) = v23;
        }
    }
}

extern "C" void kernel_launch(void* const* d_in, const int* in_sizes, int n_in,
                              void* d_out, int out_size)
{
    const float* q     = (const float*)d_in[0];
    const float* k     = (const float*)d_in[1];
    const float* v     = (const float*)d_in[2];
    const float* table = (const float*)d_in[3];
    const int*   index = (const int*)  d_in[4];
    const float* mask  = (const float*)d_in[5];
    float* out = (float*)d_out;

    gather_bias_kernel<<<256, 256>>>(table, index);
    combine_exp_kernel<<<NWH, 256>>>(mask);

    cudaFuncSetAttribute(swin_mma_kernel,
                         cudaFuncAttributeMaxDynamicSharedMemorySize, SMEM_BYTES);
    swin_mma_kernel<<<4096, TPB, SMEM_BYTES>>>(q, k, v, out);
}

// round 13
// speedup vs baseline: 5.9881x; 1.1148x over previous
#include <cuda_runtime.h>
#include <cuda_fp16.h>
#include <cstdint>

// Swin windowed attention: HMMA m16n8k16, E=exp(bias+mask-SHIFT) fp16 stored in
// FRAGMENT ORDER (no smem staging), 512-thread CTAs for 2x occupancy,
// half2 softmax via EX2.f16x2 (log2e folded into Q), lsum via ones-column PV MMA.

#define HEADS 8
#define NTOK  256
#define HD    16
#define TPB   512
#define SHIFT 4.0f
#define NWH   512
#define LOG2E 1.44269504f

__device__ float g_B[HEADS * NTOK * NTOK];        // Bh[h][ij] = table[idx,h] - SHIFT
// fragment-order exp tile: [wh][r16=16][nloc=32][lane=32] uint2
//   uint2 = { E[r16*16+g][col], E[r16*16+g+1? no: col,col+1] , E[r16*16+g+8][col..col+1] }
//   with g = lane>>2, col = nloc*8 + 2*(lane&3)
__device__ uint2 g_E2[NWH * 16 * 32 * 32];        // 67 MB

static __device__ __forceinline__ void mma16816(float c[4], const uint32_t a[4], const uint32_t b[2]) {
    asm volatile("mma.sync.aligned.m16n8k16.row.col.f32.f16.f16.f32 "
                 "{%0,%1,%2,%3}, {%4,%5,%6,%7}, {%8,%9}, {%0,%1,%2,%3};"
                 : "+f"(c[0]), "+f"(c[1]), "+f"(c[2]), "+f"(c[3])
                 : "r"(a[0]), "r"(a[1]), "r"(a[2]), "r"(a[3]), "r"(b[0]), "r"(b[1]));
}
static __device__ __forceinline__ uint32_t packh2(float x, float y) {
    __half2 h = __floats2half2_rn(x, y);
    return *reinterpret_cast<uint32_t*>(&h);
}

// ---- K1: Bh[h][ij] = table[index[ij]*8 + h] - SHIFT ----
__global__ void gather_bias_kernel(const float* __restrict__ table,
                                   const int* __restrict__ index)
{
    const int ij = blockIdx.x * 256 + threadIdx.x;
    const int idx = index[ij];
    const float4* tr = (const float4*)(table + idx * HEADS);
    float4 t0 = tr[0], t1 = tr[1];
    g_B[0 * 65536 + ij] = t0.x - SHIFT;
    g_B[1 * 65536 + ij] = t0.y - SHIFT;
    g_B[2 * 65536 + ij] = t0.z - SHIFT;
    g_B[3 * 65536 + ij] = t0.w - SHIFT;
    g_B[4 * 65536 + ij] = t1.x - SHIFT;
    g_B[5 * 65536 + ij] = t1.y - SHIFT;
    g_B[6 * 65536 + ij] = t1.z - SHIFT;
    g_B[7 * 65536 + ij] = t1.w - SHIFT;
}

// ---- K2: E2 fragment-order = exp(Bh + mask), via smem transpose ----
__global__ void combine_exp_kernel(const float* __restrict__ mask)
{
    __shared__ __half esm[16][264];
    const int wh = blockIdx.x;
    const int w = wh >> 3, h = wh & 7;
    const int tid = threadIdx.x;
    const float4* bp = (const float4*)(g_B + h * 65536);
    const float4* mp = (const float4*)(mask + (size_t)w * 65536);
    uint2* ep = g_E2 + (size_t)wh * 16384;

    for (int r16 = 0; r16 < 16; r16++) {
        const int base4 = r16 * 1024;            // float4 index of tile start
        // load + exp -> smem (coalesced reads)
        #pragma unroll
        for (int i = tid; i < 1024; i += 256) {
            const int row = i >> 6;
            const int c4 = (i & 63) * 4;
            float4 bv = bp[base4 + i];
            float4 mv = mp[base4 + i];
            *(uint2*)&esm[row][c4] = make_uint2(
                packh2(__expf(bv.x + mv.x), __expf(bv.y + mv.y)),
                packh2(__expf(bv.z + mv.z), __expf(bv.w + mv.w)));
        }
        __syncthreads();
        // write fragment order (coalesced writes)
        #pragma unroll
        for (int i = tid; i < 1024; i += 256) {
            const int nloc = i >> 5;
            const int lane = i & 31;
            const int g = lane >> 2, t4 = lane & 3;
            const int col = nloc * 8 + 2 * t4;
            uint2 o;
            o.x = *(const uint32_t*)&esm[g][col];
            o.y = *(const uint32_t*)&esm[g + 8][col];
            ep[r16 * 1024 + i] = o;
        }
        __syncthreads();
    }
}

__global__ __launch_bounds__(TPB, 2)
void swin_mma_kernel(const float* __restrict__ q, const float* __restrict__ k,
                     const float* __restrict__ v, float* __restrict__ out)
{
    __shared__ __half qh[256 * HD];
    __shared__ __half kh[256 * HD];
    __shared__ __half vth[24 * 264];    // row16 = ones (lsum), 17..23 zero

    const int t   = threadIdx.x;
    const int bid = blockIdx.x;
    const int wh  = bid >> 3;            // 8 images sharing (w,h) adjacent -> E2 L2-resident
    const int img = bid & 7;
    const int w   = wh >> 3, h = wh & 7;
    const int b   = img * 64 + w;
    const int bh  = b * HEADS + h;
    const size_t base = (size_t)bh * NTOK * HD;

    // ---- prologue: threads 0..255 stage Q,K; 256..511 stage V + ones ----
    if (t < 256) {
        const int r = t;
        {
            const float4* g = (const float4*)(q + base + (size_t)r * HD);
            float4 a0 = g[0], a1 = g[1], a2 = g[2], a3 = g[3];
            float ss = a0.x*a0.x+a0.y*a0.y+a0.z*a0.z+a0.w*a0.w + a1.x*a1.x+a1.y*a1.y+a1.z*a1.z+a1.w*a1.w
                     + a2.x*a2.x+a2.y*a2.y+a2.z*a2.z+a2.w*a2.w + a3.x*a3.x+a3.y*a3.y+a3.z*a3.z+a3.w*a3.w;
            float iv = rsqrtf(fmaxf(ss, 1e-24f)) * LOG2E;   // fold log2e into Q
            uint4 u0, u1;
            u0.x = packh2(a0.x*iv, a0.y*iv); u0.y = packh2(a0.z*iv, a0.w*iv);
            u0.z = packh2(a1.x*iv, a1.y*iv); u0.w = packh2(a1.z*iv, a1.w*iv);
            u1.x = packh2(a2.x*iv, a2.y*iv); u1.y = packh2(a2.z*iv, a2.w*iv);
            u1.z = packh2(a3.x*iv, a3.y*iv); u1.w = packh2(a3.z*iv, a3.w*iv);
            uint4* d = (uint4*)(qh + r * HD);
            d[0] = u0; d[1] = u1;
        }
        {
            const float4* g = (const float4*)(k + base + (size_t)r * HD);
            float4 a0 = g[0], a1 = g[1], a2 = g[2], a3 = g[3];
            float ss = a0.x*a0.x+a0.y*a0.y+a0.z*a0.z+a0.w*a0.w + a1.x*a1.x+a1.y*a1.y+a1.z*a1.z+a1.w*a1.w
                     + a2.x*a2.x+a2.y*a2.y+a2.z*a2.z+a2.w*a2.w + a3.x*a3.x+a3.y*a3.y+a3.z*a3.z+a3.w*a3.w;
            float iv = rsqrtf(fmaxf(ss, 1e-24f));
            uint4 u0, u1;
            u0.x = packh2(a0.x*iv, a0.y*iv); u0.y = packh2(a0.z*iv, a0.w*iv);
            u0.z = packh2(a1.x*iv, a1.y*iv); u0.w = packh2(a1.z*iv, a1.w*iv);
            u1.x = packh2(a2.x*iv, a2.y*iv); u1.y = packh2(a2.z*iv, a2.w*iv);
            u1.z = packh2(a3.x*iv, a3.y*iv); u1.w = packh2(a3.z*iv, a3.w*iv);
            uint4* d = (uint4*)(kh + r * HD);
            d[0] = u0; d[1] = u1;
        }
    } else {
        const int r = t - 256;
        const float4* g = (const float4*)(v + base + (size_t)r * HD);
        float4 a0 = g[0], a1 = g[1], a2 = g[2], a3 = g[3];
        float vd[16] = { a0.x,a0.y,a0.z,a0.w, a1.x,a1.y,a1.z,a1.w,
                         a2.x,a2.y,a2.z,a2.w, a3.x,a3.y,a3.z,a3.w };
        #pragma unroll
        for (int d = 0; d < 16; d++) vth[d * 264 + r] = __float2half_rn(vd[d]);
        for (int i = r; i < 8 * 264; i += 256) {
            const int row = 16 + i / 264, col = i % 264;
            vth[row * 264 + col] = (row == 16 && col < 256) ? __float2half_rn(1.0f)
                                                            : __float2half_rn(0.0f);
        }
    }
    __syncthreads();

    // ---- warp-synchronous main loop: 16 warps, one 16-row m-tile each ----
    const int wid  = t >> 5;
    const int lane = t & 31;
    const int g    = lane >> 2;
    const int t4   = lane & 3;
    const int qb   = wid * 16;

    uint32_t qa[4];
    {
        const int row = qb + g;
        qa[0] = *(const uint32_t*)(qh + row * HD + 2 * t4);
        qa[1] = *(const uint32_t*)(qh + (row + 8) * HD + 2 * t4);
        qa[2] = *(const uint32_t*)(qh + row * HD + 2 * t4 + 8);
        qa[3] = *(const uint32_t*)(qh + (row + 8) * HD + 2 * t4 + 8);
    }

    float o[3][4];   // nd=2 is lsum (ones) tile
    #pragma unroll
    for (int n = 0; n < 3; n++)
        #pragma unroll
        for (int i = 0; i < 4; i++) o[n][i] = 0.f;

    const uint2* Ep = g_E2 + (size_t)wh * 16384 + wid * 1024 + lane;

    #pragma unroll 4
    for (int kk = 0; kk < 16; kk++) {
        // E fragment loads (independent of MMA chain -> hides latency)
        uint2 e0 = Ep[(kk * 2 + 0) * 32];
        uint2 e1 = Ep[(kk * 2 + 1) * 32];

        float s[2][4];
        #pragma unroll
        for (int nl = 0; nl < 2; nl++) {
            const int key = kk * 16 + nl * 8 + g;
            uint32_t kb[2];
            kb[0] = *(const uint32_t*)(kh + key * HD + 2 * t4);
            kb[1] = *(const uint32_t*)(kh + key * HD + 2 * t4 + 8);
            s[nl][0] = s[nl][1] = s[nl][2] = s[nl][3] = 0.f;
            mma16816(s[nl], qa, kb);
        }
        // half2 softmax: p = 2^s * E
        uint32_t pa[4];
        #pragma unroll
        for (int nl = 0; nl < 2; nl++) {
            const uint2 e = nl ? e1 : e0;
            __half2 e01 = *(const __half2*)&e.x;
            __half2 e23 = *(const __half2*)&e.y;
            __half2 s01 = __floats2half2_rn(s[nl][0], s[nl][1]);
            __half2 s23 = __floats2half2_rn(s[nl][2], s[nl][3]);
            __half2 p01 = __hmul2(h2exp2(s01), e01);
            __half2 p23 = __hmul2(h2exp2(s23), e23);
            pa[nl * 2 + 0] = *reinterpret_cast<uint32_t*>(&p01);
            pa[nl * 2 + 1] = *reinterpret_cast<uint32_t*>(&p23);
        }
        // PV + lsum: 3 n-tiles (dims 0-7, 8-15, ones@16)
        #pragma unroll
        for (int nd = 0; nd < 3; nd++) {
            const int dim = nd * 8 + g;
            uint32_t vb[2];
            vb[0] = *(const uint32_t*)(vth + dim * 264 + kk * 16 + 2 * t4);
            vb[1] = *(const uint32_t*)(vth + dim * 264 + kk * 16 + 2 * t4 + 8);
            mma16816(o[nd], pa, vb);
        }
    }

    // ---- epilogue: lsum in ones-column (col16: c0/c2 of t4==0) ----
    {
        const float l0 = __shfl_sync(0xFFFFFFFF, o[2][0], lane & ~3);
        const float l1 = __shfl_sync(0xFFFFFFFF, o[2][2], lane & ~3);
        const float inv0 = 1.0f / l0;
        const float inv1 = 1.0f / l1;
        const int row = qb + g;
        #pragma unroll
        for (int nd = 0; nd < 2; nd++) {
            const int col = h * HD + nd * 8 + 2 * t4;
            float2 v01 = { o[nd][0] * inv0, o[nd][1] * inv0 };
            float2 v23 = { o[nd][2] * inv1, o[nd][3] * inv1 };
            *(float2*)(out + ((size_t)(b * NTOK + row)) * 128 + col)     = v01;
            *(float2*)(out + ((size_t)(b * NTOK + row + 8)) * 128 + col) = v23;
        }
    }
}

extern "C" void kernel_launch(void* const* d_in, const int* in_sizes, int n_in,
                              void* d_out, int out_size)
{
    const float* q     = (const float*)d_in[0];
    const float* k     = (const float*)d_in[1];
    const float* v     = (const float*)d_in[2];
    const float* table = (const float*)d_in[3];
    const int*   index = (const int*)  d_in[4];
    const float* mask  = (const float*)d_in[5];
    float* out = (float*)d_out;

    gather_bias_kernel<<<256, 256>>>(table, index);
    combine_exp_kernel<<<NWH, 256>>>(mask);
    swin_mma_kernel<<<4096, TPB>>>(q, k, v, out);
}

// round 14
// speedup vs baseline: 6.5395x; 1.0921x over previous
#include <cuda_runtime.h>
#include <cuda_fp16.h>
#include <cstdint>

// Swin windowed attention: HMMA m16n8k16 (QK in fp16-acc, PV fp32-acc),
// E=exp(bias+mask-SHIFT) fp16 in fragment order, paired-fragment K/V smem layouts,
// 512-thread CTAs, lsum via ones-column PV MMA.

#define HEADS 8
#define NTOK  256
#define HD    16
#define TPB   512
#define SHIFT 4.0f
#define NWH   512
#define LOG2E 1.44269504f

__device__ float g_B[HEADS * NTOK * NTOK];        // Bh[h][ij] = table[idx,h] - SHIFT
__device__ uint2 g_E2[NWH * 16 * 32 * 32];        // fragment-order exp tiles (67 MB)

#define VSTR 272   // Vt row stride (halves): conflict-free LDS.64

static __device__ __forceinline__ void mma_f32(float c[4], const uint32_t a[4], const uint32_t b[2]) {
    asm volatile("mma.sync.aligned.m16n8k16.row.col.f32.f16.f16.f32 "
                 "{%0,%1,%2,%3}, {%4,%5,%6,%7}, {%8,%9}, {%0,%1,%2,%3};"
                 : "+f"(c[0]), "+f"(c[1]), "+f"(c[2]), "+f"(c[3])
                 : "r"(a[0]), "r"(a[1]), "r"(a[2]), "r"(a[3]), "r"(b[0]), "r"(b[1]));
}
static __device__ __forceinline__ void mma_f16(uint32_t c[2], const uint32_t a[4], const uint32_t b[2]) {
    asm volatile("mma.sync.aligned.m16n8k16.row.col.f16.f16.f16.f16 "
                 "{%0,%1}, {%2,%3,%4,%5}, {%6,%7}, {%0,%1};"
                 : "+r"(c[0]), "+r"(c[1])
                 : "r"(a[0]), "r"(a[1]), "r"(a[2]), "r"(a[3]), "r"(b[0]), "r"(b[1]));
}
static __device__ __forceinline__ uint32_t packh2(float x, float y) {
    __half2 h = __floats2half2_rn(x, y);
    return *reinterpret_cast<uint32_t*>(&h);
}

// ---- K1: Bh[h][ij] = table[index[ij]*8 + h] - SHIFT ----
__global__ void gather_bias_kernel(const float* __restrict__ table,
                                   const int* __restrict__ index)
{
    const int ij = blockIdx.x * 256 + threadIdx.x;
    const int idx = index[ij];
    const float4* tr = (const float4*)(table + idx * HEADS);
    float4 t0 = tr[0], t1 = tr[1];
    g_B[0 * 65536 + ij] = t0.x - SHIFT;
    g_B[1 * 65536 + ij] = t0.y - SHIFT;
    g_B[2 * 65536 + ij] = t0.z - SHIFT;
    g_B[3 * 65536 + ij] = t0.w - SHIFT;
    g_B[4 * 65536 + ij] = t1.x - SHIFT;
    g_B[5 * 65536 + ij] = t1.y - SHIFT;
    g_B[6 * 65536 + ij] = t1.z - SHIFT;
    g_B[7 * 65536 + ij] = t1.w - SHIFT;
}

// ---- K2: E2 fragment-order = exp(Bh + mask), via smem transpose ----
__global__ void combine_exp_kernel(const float* __restrict__ mask)
{
    __shared__ __half esm[16][264];
    const int wh = blockIdx.x;
    const int w = wh >> 3, h = wh & 7;
    const int tid = threadIdx.x;
    const float4* bp = (const float4*)(g_B + h * 65536);
    const float4* mp = (const float4*)(mask + (size_t)w * 65536);
    uint2* ep = g_E2 + (size_t)wh * 16384;

    for (int r16 = 0; r16 < 16; r16++) {
        const int base4 = r16 * 1024;
        #pragma unroll
        for (int i = tid; i < 1024; i += 256) {
            const int row = i >> 6;
            const int c4 = (i & 63) * 4;
            float4 bv = bp[base4 + i];
            float4 mv = mp[base4 + i];
            *(uint2*)&esm[row][c4] = make_uint2(
                packh2(__expf(bv.x + mv.x), __expf(bv.y + mv.y)),
                packh2(__expf(bv.z + mv.z), __expf(bv.w + mv.w)));
        }
        __syncthreads();
        #pragma unroll
        for (int i = tid; i < 1024; i += 256) {
            const int nloc = i >> 5;
            const int lane = i & 31;
            const int g = lane >> 2, t4 = lane & 3;
            const int col = nloc * 8 + 2 * t4;
            uint2 o;
            o.x = *(const uint32_t*)&esm[g][col];
            o.y = *(const uint32_t*)&esm[g + 8][col];
            ep[r16 * 1024 + i] = o;
        }
        __syncthreads();
    }
}

__global__ __launch_bounds__(TPB, 2)
void swin_mma_kernel(const float* __restrict__ q, const float* __restrict__ k,
                     const float* __restrict__ v, float* __restrict__ out)
{
    __shared__ __half qh[256 * HD];          // original d-order (A frags)
    __shared__ __half kh[256 * HD];          // paired d-order: [0,1,8,9, 2,3,10,11, ...]
    __shared__ __half vth[24 * VSTR];        // key-paired within 16-groups; row16 = ones

    const int t   = threadIdx.x;
    const int bid = blockIdx.x;
    const int wh  = bid >> 3;            // 8 images sharing (w,h) adjacent -> E2 L2-resident
    const int img = bid & 7;
    const int w   = wh >> 3, h = wh & 7;
    const int b   = img * 64 + w;
    const int bh  = b * HEADS + h;
    const size_t base = (size_t)bh * NTOK * HD;

    // ---- prologue ----
    if (t < 256) {
        const int r = t;
        {   // Q normalized * log2e, original layout
            const float4* g = (const float4*)(q + base + (size_t)r * HD);
            float4 a0 = g[0], a1 = g[1], a2 = g[2], a3 = g[3];
            float ss = a0.x*a0.x+a0.y*a0.y+a0.z*a0.z+a0.w*a0.w + a1.x*a1.x+a1.y*a1.y+a1.z*a1.z+a1.w*a1.w
                     + a2.x*a2.x+a2.y*a2.y+a2.z*a2.z+a2.w*a2.w + a3.x*a3.x+a3.y*a3.y+a3.z*a3.z+a3.w*a3.w;
            float iv = rsqrtf(fmaxf(ss, 1e-24f)) * LOG2E;
            uint4 u0, u1;
            u0.x = packh2(a0.x*iv, a0.y*iv); u0.y = packh2(a0.z*iv, a0.w*iv);
            u0.z = packh2(a1.x*iv, a1.y*iv); u0.w = packh2(a1.z*iv, a1.w*iv);
            u1.x = packh2(a2.x*iv, a2.y*iv); u1.y = packh2(a2.z*iv, a2.w*iv);
            u1.z = packh2(a3.x*iv, a3.y*iv); u1.w = packh2(a3.z*iv, a3.w*iv);
            uint4* d = (uint4*)(qh + r * HD);
            d[0] = u0; d[1] = u1;
        }
        {   // K normalized, paired d-order for LDS.64 B-fragments
            const float4* g = (const float4*)(k + base + (size_t)r * HD);
            float4 a0 = g[0], a1 = g[1], a2 = g[2], a3 = g[3];
            float ss = a0.x*a0.x+a0.y*a0.y+a0.z*a0.z+a0.w*a0.w + a1.x*a1.x+a1.y*a1.y+a1.z*a1.z+a1.w*a1.w
                     + a2.x*a2.x+a2.y*a2.y+a2.z*a2.z+a2.w*a2.w + a3.x*a3.x+a3.y*a3.y+a3.z*a3.z+a3.w*a3.w;
            float iv = rsqrtf(fmaxf(ss, 1e-24f));
            uint32_t d01 = packh2(a0.x*iv, a0.y*iv), d23 = packh2(a0.z*iv, a0.w*iv);
            uint32_t d45 = packh2(a1.x*iv, a1.y*iv), d67 = packh2(a1.z*iv, a1.w*iv);
            uint32_t d89 = packh2(a2.x*iv, a2.y*iv), dAB = packh2(a2.z*iv, a2.w*iv);
            uint32_t dCD = packh2(a3.x*iv, a3.y*iv), dEF = packh2(a3.z*iv, a3.w*iv);
            uint4* d = (uint4*)(kh + r * HD);
            d[0] = make_uint4(d01, d89, d23, dAB);   // t4=0: d0d1,d8d9 ; t4=1: d2d3,d10d11
            d[1] = make_uint4(d45, dCD, d67, dEF);   // t4=2, t4=3
        }
    } else {
        const int r = t - 256;   // key index
        const float4* g = (const float4*)(v + base + (size_t)r * HD);
        float4 a0 = g[0], a1 = g[1], a2 = g[2], a3 = g[3];
        float vd[16] = { a0.x,a0.y,a0.z,a0.w, a1.x,a1.y,a1.z,a1.w,
                         a2.x,a2.y,a2.z,a2.w, a3.x,a3.y,a3.z,a3.w };
        // paired key slot within each 16-key group: keys [0,1,8,9,2,3,10,11,4,5,12,13,6,7,14,15]
        const int slot = ((r & 7) >> 1) * 4 + (r & 1) + ((r >> 3) & 1) * 2;
        const int col  = (r >> 4) * 16 + slot;
        #pragma unroll
        for (int d = 0; d < 16; d++) vth[d * VSTR + col] = __float2half_rn(vd[d]);
        for (int i = r; i < 8 * VSTR; i += 256) {
            const int row = 16 + i / VSTR, cc = i % VSTR;
            vth[row * VSTR + cc] = (row == 16 && cc < 256) ? __float2half_rn(1.0f)
                                                           : __float2half_rn(0.0f);
        }
    }
    __syncthreads();

    // ---- warp-synchronous main loop: 16 warps, one 16-row m-tile each ----
    const int wid  = t >> 5;
    const int lane = t & 31;
    const int g    = lane >> 2;
    const int t4   = lane & 3;
    const int qb   = wid * 16;

    uint32_t qa[4];
    {
        const int row = qb + g;
        qa[0] = *(const uint32_t*)(qh + row * HD + 2 * t4);
        qa[1] = *(const uint32_t*)(qh + (row + 8) * HD + 2 * t4);
        qa[2] = *(const uint32_t*)(qh + row * HD + 2 * t4 + 8);
        qa[3] = *(const uint32_t*)(qh + (row + 8) * HD + 2 * t4 + 8);
    }

    float o[3][4];   // nd=2 is lsum (ones) tile
    #pragma unroll
    for (int n = 0; n < 3; n++)
        #pragma unroll
        for (int i = 0; i < 4; i++) o[n][i] = 0.f;

    const uint2* Ep = g_E2 + (size_t)wh * 16384 + wid * 1024 + lane;
    const __half* khf = kh;
    const __half* vtf = vth;

    #pragma unroll 4
    for (int kk = 0; kk < 16; kk++) {
        uint2 e0 = Ep[(kk * 2 + 0) * 32];
        uint2 e1 = Ep[(kk * 2 + 1) * 32];

        uint32_t pa[4];
        #pragma unroll
        for (int nl = 0; nl < 2; nl++) {
            const int key = kk * 16 + nl * 8 + g;
            uint2 kb2 = *(const uint2*)(khf + key * HD + t4 * 4);   // paired frag, LDS.64
            uint32_t kb[2] = { kb2.x, kb2.y };
            uint32_t sd[2] = { 0u, 0u };                            // fp16 accum
            mma_f16(sd, qa, kb);
            const uint2 e = nl ? e1 : e0;
            __half2 p01 = __hmul2(h2exp2(*(const __half2*)&sd[0]), *(const __half2*)&e.x);
            __half2 p23 = __hmul2(h2exp2(*(const __half2*)&sd[1]), *(const __half2*)&e.y);
            pa[nl * 2 + 0] = *reinterpret_cast<uint32_t*>(&p01);
            pa[nl * 2 + 1] = *reinterpret_cast<uint32_t*>(&p23);
        }
        // PV + lsum: 3 n-tiles (dims 0-7, 8-15, ones@16), fp32 accum
        #pragma unroll
        for (int nd = 0; nd < 3; nd++) {
            const int dim = nd * 8 + g;
            uint2 vb2 = *(const uint2*)(vtf + dim * VSTR + kk * 16 + t4 * 4);  // paired, LDS.64
            uint32_t vb[2] = { vb2.x, vb2.y };
            mma_f32(o[nd], pa, vb);
        }
    }

    // ---- epilogue: lsum in ones-column (col16: c0/c2 of t4==0) ----
    {
        const float l0 = __shfl_sync(0xFFFFFFFF, o[2][0], lane & ~3);
        const float l1 = __shfl_sync(0xFFFFFFFF, o[2][2], lane & ~3);
        const float inv0 = 1.0f / l0;
        const float inv1 = 1.0f / l1;
        const int row = qb + g;
        #pragma unroll
        for (int nd = 0; nd < 2; nd++) {
            const int col = h * HD + nd * 8 + 2 * t4;
            float2 v01 = { o[nd][0] * inv0, o[nd][1] * inv0 };
            float2 v23 = { o[nd][2] * inv1, o[nd][3] * inv1 };
            *(float2*)(out + ((size_t)(b * NTOK + row)) * 128 + col)     = v01;
            *(float2*)(out + ((size_t)(b * NTOK + row + 8)) * 128 + col) = v23;
        }
    }
}

extern "C" void kernel_launch(void* const* d_in, const int* in_sizes, int n_in,
                              void* d_out, int out_size)
{
    const float* q     = (const float*)d_in[0];
    const float* k     = (const float*)d_in[1];
    const float* v     = (const float*)d_in[2];
    const float* table = (const float*)d_in[3];
    const int*   index = (const int*)  d_in[4];
    const float* mask  = (const float*)d_in[5];
    float* out = (float*)d_out;

    gather_bias_kernel<<<256, 256>>>(table, index);
    combine_exp_kernel<<<NWH, 256>>>(mask);
    swin_mma_kernel<<<4096, TPB>>>(q, k, v, out);
}